// round 1
// baseline (speedup 1.0000x reference)
#include <cuda_runtime.h>

#define N_NODES 100000
#define N_EDGES 1600000
#define HID 128
#define NCLS 47

// ---------------- scratch (static device globals; no runtime allocation) ----
__device__ float g_y  [(size_t)N_NODES * HID];   // GEMM output / scatter source
__device__ float g_agg[(size_t)N_NODES * HID];   // scatter accumulation
__device__ float g_h  [(size_t)N_NODES * HID];   // post-activation hidden
__device__ float g_cs [N_NODES];                 // c_src = max(out_deg,1)^-0.5
__device__ float g_cd [N_NODES];                 // c_dst = max(in_deg,1)^-0.5

// ---------------- degree pipeline ------------------------------------------
__global__ void zero_deg_kernel() {
    int i = blockIdx.x * blockDim.x + threadIdx.x;
    if (i < N_NODES) { g_cs[i] = 0.f; g_cd[i] = 0.f; }
}

__global__ void degree_kernel(const int* __restrict__ edges) {
    int i = blockIdx.x * blockDim.x + threadIdx.x;
    if (i < N_EDGES) {
        atomicAdd(&g_cs[edges[i]], 1.f);            // src -> out degree
        atomicAdd(&g_cd[edges[N_EDGES + i]], 1.f);  // dst -> in degree
    }
}

__global__ void finish_deg_kernel() {
    int i = blockIdx.x * blockDim.x + threadIdx.x;
    if (i < N_NODES) {
        g_cs[i] = rsqrtf(fmaxf(g_cs[i], 1.f));
        g_cd[i] = rsqrtf(fmaxf(g_cd[i], 1.f));
    }
}

// ---------------- zero the aggregation buffer ------------------------------
__global__ void zero_agg_kernel() {
    int i = blockIdx.x * blockDim.x + threadIdx.x;   // over N_NODES*32 float4
    if (i < N_NODES * 32) {
        float4 z = make_float4(0.f, 0.f, 0.f, 0.f);
        ((float4*)g_agg)[i] = z;
    }
}

// ---------------- main GEMM: Y = (A * c_src[:,None]) @ W  (K=N=128) --------
// Tile: 64 rows x 128 cols, BK=32. 256 threads, 4x8 register tile each.
__global__ void __launch_bounds__(256) gemm128_kernel(
    const float* __restrict__ X, int useH,
    const float* __restrict__ W, int M)
{
    const float* A = useH ? (const float*)g_h : X;

    __shared__ float As[32][68];   // [k][row], padded stride 68 (16B-aligned, conflict-free)
    __shared__ float Bs[32][128];  // [k][col]

    int tid  = threadIdx.x;
    int row0 = blockIdx.x * 64;
    int tix  = tid & 15;           // col group: 8 cols
    int tiy  = tid >> 4;           // row group: 4 rows

    float acc[4][8];
#pragma unroll
    for (int i = 0; i < 4; i++)
#pragma unroll
        for (int j = 0; j < 8; j++) acc[i][j] = 0.f;

    for (int k0 = 0; k0 < 128; k0 += 32) {
        // load A chunk: 64 rows x 32 k = 512 float4 tasks, 2 per thread; scale by c_src
#pragma unroll
        for (int t = 0; t < 2; t++) {
            int id   = tid + t * 256;
            int r    = id >> 3;            // 0..63
            int kk4  = (id & 7) * 4;       // 0,4,...,28
            int grow = row0 + r;
            float4 v = make_float4(0.f, 0.f, 0.f, 0.f);
            float  s = 0.f;
            if (grow < M) {
                v = *(const float4*)(A + (size_t)grow * 128 + k0 + kk4);
                s = g_cs[grow];
            }
            As[kk4 + 0][r] = v.x * s;
            As[kk4 + 1][r] = v.y * s;
            As[kk4 + 2][r] = v.z * s;
            As[kk4 + 3][r] = v.w * s;
        }
        // load W chunk: 32 k x 128 cols = 1024 float4 tasks, 4 per thread
#pragma unroll
        for (int t = 0; t < 4; t++) {
            int id = tid + t * 256;
            int kk = id >> 5;              // 0..31
            int n4 = (id & 31) * 4;
            *(float4*)&Bs[kk][n4] = *(const float4*)(W + (size_t)(k0 + kk) * 128 + n4);
        }
        __syncthreads();

#pragma unroll
        for (int kk = 0; kk < 32; kk++) {
            float4 a  = *(float4*)&As[kk][tiy * 4];
            float4 b0 = *(float4*)&Bs[kk][tix * 8];
            float4 b1 = *(float4*)&Bs[kk][tix * 8 + 4];
            float av[4] = {a.x, a.y, a.z, a.w};
            float bv[8] = {b0.x, b0.y, b0.z, b0.w, b1.x, b1.y, b1.z, b1.w};
#pragma unroll
            for (int i = 0; i < 4; i++)
#pragma unroll
                for (int j = 0; j < 8; j++)
                    acc[i][j] = fmaf(av[i], bv[j], acc[i][j]);
        }
        __syncthreads();
    }

#pragma unroll
    for (int i = 0; i < 4; i++) {
        int row = row0 + tiy * 4 + i;
        if (row < M) {
            float4 o0 = make_float4(acc[i][0], acc[i][1], acc[i][2], acc[i][3]);
            float4 o1 = make_float4(acc[i][4], acc[i][5], acc[i][6], acc[i][7]);
            *(float4*)(g_y + (size_t)row * 128 + tix * 8)     = o0;
            *(float4*)(g_y + (size_t)row * 128 + tix * 8 + 4) = o1;
        }
    }
}

// ---------------- edge scatter: g_agg[dst] += g_y[src] ---------------------
// one warp per edge; lane handles 4 consecutive floats (float4 gather + 4 REDs)
__global__ void __launch_bounds__(256) scatter_kernel(const int* __restrict__ edges) {
    int w    = (blockIdx.x * 256 + threadIdx.x) >> 5;
    int lane = threadIdx.x & 31;
    if (w >= N_EDGES) return;
    int s = __ldg(edges + w);
    int d = __ldg(edges + N_EDGES + w);
    float4 v = *(const float4*)(g_y + (size_t)s * 128 + lane * 4);
    float* o = g_agg + (size_t)d * 128 + lane * 4;
    atomicAdd(o + 0, v.x);
    atomicAdd(o + 1, v.y);
    atomicAdd(o + 2, v.z);
    atomicAdd(o + 3, v.w);
}

// ---------------- epilogue: g_h = relu(g_agg * c_dst + b) ------------------
__global__ void post_kernel(const float* __restrict__ b) {
    int i = blockIdx.x * blockDim.x + threadIdx.x;   // over N_NODES*32 float4
    if (i < N_NODES * 32) {
        int node = i >> 5;
        float c  = g_cd[node];
        int col  = (i & 31) * 4;
        float4 v  = ((const float4*)g_agg)[i];
        float4 bb = *(const float4*)(b + col);
        float4 r;
        r.x = fmaxf(fmaf(v.x, c, bb.x), 0.f);
        r.y = fmaxf(fmaf(v.y, c, bb.y), 0.f);
        r.z = fmaxf(fmaf(v.z, c, bb.z), 0.f);
        r.w = fmaxf(fmaf(v.w, c, bb.w), 0.f);
        ((float4*)g_h)[i] = r;
    }
}

// ---------------- classifier: out = g_h @ Wc + bc  (N=47, K=128) -----------
// 16 rows/block, 256 threads laid out (64,4); tx<47 columns, 4 rows each.
__global__ void __launch_bounds__(256) cls_kernel(
    const float* __restrict__ Wc, const float* __restrict__ bc,
    float* __restrict__ out, int M)
{
    __shared__ float Hs[16][128];
    __shared__ float Wcs[128][48];

    int tid  = threadIdx.x;
    int row0 = blockIdx.x * 16;

    for (int id = tid; id < 128 * NCLS; id += 256)
        Wcs[id / NCLS][id % NCLS] = Wc[id];

#pragma unroll
    for (int t = 0; t < 2; t++) {
        int id = tid + t * 256;          // 0..511
        int m  = id >> 5;                // 0..15
        int k4 = (id & 31) * 4;
        int row = row0 + m;
        float4 v = make_float4(0.f, 0.f, 0.f, 0.f);
        if (row < M) v = *(const float4*)(g_h + (size_t)row * 128 + k4);
        *(float4*)&Hs[m][k4] = v;
    }
    __syncthreads();

    int tx = tid & 63;
    int ty = tid >> 6;
    if (tx < NCLS) {
        float acc[4] = {0.f, 0.f, 0.f, 0.f};
#pragma unroll 4
        for (int k = 0; k < 128; k++) {
            float w = Wcs[k][tx];
#pragma unroll
            for (int i = 0; i < 4; i++)
                acc[i] = fmaf(Hs[ty * 4 + i][k], w, acc[i]);
        }
        float bias = bc[tx];
#pragma unroll
        for (int i = 0; i < 4; i++) {
            int row = row0 + ty * 4 + i;
            if (row < M) out[(size_t)row * NCLS + tx] = acc[i] + bias;
        }
    }
}

// ---------------- launch ----------------------------------------------------
extern "C" void kernel_launch(void* const* d_in, const int* in_sizes, int n_in,
                              void* d_out, int out_size)
{
    const float* x     = (const float*)d_in[0];
    const int*   edges = (const int*)  d_in[1];
    const float* W0    = (const float*)d_in[2];
    const float* b0    = (const float*)d_in[3];
    const float* W1    = (const float*)d_in[4];
    const float* b1    = (const float*)d_in[5];
    const float* Wc    = (const float*)d_in[6];
    const float* bc    = (const float*)d_in[7];
    float* out = (float*)d_out;

    const int nodeBlocks = (N_NODES + 255) / 256;          // 391
    const int edgeBlocks = (N_EDGES + 255) / 256;          // 6250
    const int vecBlocks  = (N_NODES * 32 + 255) / 256;     // 12500
    const int gemmBlocks = (N_NODES + 63) / 64;            // 1563
    const int scatBlocks = (N_EDGES * 32 + 255) / 256;     // 200000
    const int clsBlocks  = (N_NODES + 15) / 16;            // 6250

    // normalization coefficients
    zero_deg_kernel<<<nodeBlocks, 256>>>();
    degree_kernel<<<edgeBlocks, 256>>>(edges);
    finish_deg_kernel<<<nodeBlocks, 256>>>();

    // layer 0
    gemm128_kernel<<<gemmBlocks, 256>>>(x, 0, W0, N_NODES);
    zero_agg_kernel<<<vecBlocks, 256>>>();
    scatter_kernel<<<scatBlocks, 256>>>(edges);
    post_kernel<<<vecBlocks, 256>>>(b0);

    // layer 1
    gemm128_kernel<<<gemmBlocks, 256>>>(nullptr, 1, W1, N_NODES);
    zero_agg_kernel<<<vecBlocks, 256>>>();
    scatter_kernel<<<scatBlocks, 256>>>(edges);
    post_kernel<<<vecBlocks, 256>>>(b1);

    // classifier
    cls_kernel<<<clsBlocks, 256>>>(Wc, bc, out, N_NODES);
}

// round 5
// speedup vs baseline: 2.0935x; 2.0935x over previous
#include <cuda_runtime.h>

#define N_NODES 100000
#define N_EDGES 1600000
#define HID 128
#define NCLS 47

// ---------------- scratch (static device globals; no runtime allocation) ----
__device__ float g_y  [(size_t)N_NODES * HID];   // GEMM output / gather source
__device__ float g_h  [(size_t)N_NODES * HID];   // post-activation hidden
__device__ float g_cs [N_NODES];                 // c_src = max(out_deg,1)^-0.5
__device__ float g_cd [N_NODES];                 // c_dst = max(in_deg,1)^-0.5
__device__ int   g_outdeg[N_NODES];
__device__ int   g_indeg [N_NODES];
__device__ int   g_cursor[N_NODES];
__device__ int   g_rowstart[N_NODES + 1];
__device__ int   g_csrc[N_EDGES];                // CSR: src ids grouped by dst

// ---------------- degree / CSR pipeline ------------------------------------
__global__ void zero_counts_kernel() {
    int i = blockIdx.x * blockDim.x + threadIdx.x;
    if (i < N_NODES) { g_outdeg[i] = 0; g_indeg[i] = 0; g_cursor[i] = 0; }
}

__global__ void degree_kernel(const int* __restrict__ edges) {
    int i = blockIdx.x * blockDim.x + threadIdx.x;
    if (i < N_EDGES) {
        atomicAdd(&g_outdeg[edges[i]], 1);
        atomicAdd(&g_indeg [edges[N_EDGES + i]], 1);
    }
}

__global__ void finish_deg_kernel() {
    int i = blockIdx.x * blockDim.x + threadIdx.x;
    if (i < N_NODES) {
        g_cs[i] = rsqrtf(fmaxf((float)g_outdeg[i], 1.f));
        g_cd[i] = rsqrtf(fmaxf((float)g_indeg[i],  1.f));
    }
}

// single-block chunked exclusive scan of g_indeg -> g_rowstart
__global__ void __launch_bounds__(1024) scan_kernel() {
    __shared__ int part[1024];
    const int CH = (N_NODES + 1023) / 1024;  // 98
    int t   = threadIdx.x;
    int beg = t * CH;
    int end = min(beg + CH, N_NODES);
    int s = 0;
    for (int i = beg; i < end; i++) s += g_indeg[i];
    part[t] = s;
    __syncthreads();
    // Hillis-Steele inclusive scan over 1024 partials
    for (int off = 1; off < 1024; off <<= 1) {
        int v = (t >= off) ? part[t - off] : 0;
        __syncthreads();
        part[t] += v;
        __syncthreads();
    }
    int excl = (t == 0) ? 0 : part[t - 1];
    for (int i = beg; i < end; i++) {
        g_rowstart[i] = excl;
        excl += g_indeg[i];
    }
    if (t == 1023) g_rowstart[N_NODES] = N_EDGES;
}

__global__ void fill_csr_kernel(const int* __restrict__ edges) {
    int i = blockIdx.x * blockDim.x + threadIdx.x;
    if (i < N_EDGES) {
        int s = edges[i];
        int d = edges[N_EDGES + i];
        int pos = g_rowstart[d] + atomicAdd(&g_cursor[d], 1);
        g_csrc[pos] = s;
    }
}

// ---------------- main GEMM: Y = (A * c_src[:,None]) @ W  (K=N=128) --------
// Tile: 64 rows x 128 cols, BK=32. 256 threads, 4x8 register tile each.
__global__ void __launch_bounds__(256) gemm128_kernel(
    const float* __restrict__ X, int useH,
    const float* __restrict__ W, int M)
{
    const float* A = useH ? (const float*)g_h : X;

    __shared__ float As[32][68];   // [k][row], padded
    __shared__ float Bs[32][128];  // [k][col]

    int tid  = threadIdx.x;
    int row0 = blockIdx.x * 64;
    int tix  = tid & 15;           // col group: 8 cols
    int tiy  = tid >> 4;           // row group: 4 rows

    float acc[4][8];
#pragma unroll
    for (int i = 0; i < 4; i++)
#pragma unroll
        for (int j = 0; j < 8; j++) acc[i][j] = 0.f;

    for (int k0 = 0; k0 < 128; k0 += 32) {
#pragma unroll
        for (int t = 0; t < 2; t++) {
            int id   = tid + t * 256;
            int r    = id >> 3;
            int kk4  = (id & 7) * 4;
            int grow = row0 + r;
            float4 v = make_float4(0.f, 0.f, 0.f, 0.f);
            float  s = 0.f;
            if (grow < M) {
                v = *(const float4*)(A + (size_t)grow * 128 + k0 + kk4);
                s = g_cs[grow];
            }
            As[kk4 + 0][r] = v.x * s;
            As[kk4 + 1][r] = v.y * s;
            As[kk4 + 2][r] = v.z * s;
            As[kk4 + 3][r] = v.w * s;
        }
#pragma unroll
        for (int t = 0; t < 4; t++) {
            int id = tid + t * 256;
            int kk = id >> 5;
            int n4 = (id & 31) * 4;
            *(float4*)&Bs[kk][n4] = *(const float4*)(W + (size_t)(k0 + kk) * 128 + n4);
        }
        __syncthreads();

#pragma unroll
        for (int kk = 0; kk < 32; kk++) {
            float4 a  = *(float4*)&As[kk][tiy * 4];
            float4 b0 = *(float4*)&Bs[kk][tix * 8];
            float4 b1 = *(float4*)&Bs[kk][tix * 8 + 4];
            float av[4] = {a.x, a.y, a.z, a.w};
            float bv[8] = {b0.x, b0.y, b0.z, b0.w, b1.x, b1.y, b1.z, b1.w};
#pragma unroll
            for (int i = 0; i < 4; i++)
#pragma unroll
                for (int j = 0; j < 8; j++)
                    acc[i][j] = fmaf(av[i], bv[j], acc[i][j]);
        }
        __syncthreads();
    }

#pragma unroll
    for (int i = 0; i < 4; i++) {
        int row = row0 + tiy * 4 + i;
        if (row < M) {
            float4 o0 = make_float4(acc[i][0], acc[i][1], acc[i][2], acc[i][3]);
            float4 o1 = make_float4(acc[i][4], acc[i][5], acc[i][6], acc[i][7]);
            *(float4*)(g_y + (size_t)row * 128 + tix * 8)     = o0;
            *(float4*)(g_y + (size_t)row * 128 + tix * 8 + 4) = o1;
        }
    }
}

// ---------------- CSR gather + scale + bias + relu (fused) -----------------
// one warp per dst node; lane owns 4 consecutive feature floats.
__global__ void __launch_bounds__(256) gather_kernel(const float* __restrict__ b) {
    int w    = blockIdx.x * 8 + (threadIdx.x >> 5);
    int lane = threadIdx.x & 31;
    if (w >= N_NODES) return;

    int beg = __ldg(&g_rowstart[w]);
    int end = __ldg(&g_rowstart[w + 1]);

    float4 acc = make_float4(0.f, 0.f, 0.f, 0.f);

    for (int base = beg; base < end; base += 32) {
        int n   = end - base;
        int m   = n < 32 ? n : 32;
        int idx = (lane < m) ? __ldg(&g_csrc[base + lane]) : 0;

        int j = 0;
        for (; j + 4 <= m; j += 4) {
            int s0 = __shfl_sync(0xffffffffu, idx, j + 0);
            int s1 = __shfl_sync(0xffffffffu, idx, j + 1);
            int s2 = __shfl_sync(0xffffffffu, idx, j + 2);
            int s3 = __shfl_sync(0xffffffffu, idx, j + 3);
            float4 v0 = *(const float4*)(g_y + (size_t)s0 * 128 + lane * 4);
            float4 v1 = *(const float4*)(g_y + (size_t)s1 * 128 + lane * 4);
            float4 v2 = *(const float4*)(g_y + (size_t)s2 * 128 + lane * 4);
            float4 v3 = *(const float4*)(g_y + (size_t)s3 * 128 + lane * 4);
            acc.x += (v0.x + v1.x) + (v2.x + v3.x);
            acc.y += (v0.y + v1.y) + (v2.y + v3.y);
            acc.z += (v0.z + v1.z) + (v2.z + v3.z);
            acc.w += (v0.w + v1.w) + (v2.w + v3.w);
        }
        for (; j < m; j++) {
            int s = __shfl_sync(0xffffffffu, idx, j);
            float4 v = *(const float4*)(g_y + (size_t)s * 128 + lane * 4);
            acc.x += v.x; acc.y += v.y; acc.z += v.z; acc.w += v.w;
        }
    }

    float c = g_cd[w];
    float4 bb = *(const float4*)(b + lane * 4);
    float4 r;
    r.x = fmaxf(fmaf(acc.x, c, bb.x), 0.f);
    r.y = fmaxf(fmaf(acc.y, c, bb.y), 0.f);
    r.z = fmaxf(fmaf(acc.z, c, bb.z), 0.f);
    r.w = fmaxf(fmaf(acc.w, c, bb.w), 0.f);
    *(float4*)(g_h + (size_t)w * 128 + lane * 4) = r;
}

// ---------------- classifier: out = g_h @ Wc + bc  (N=47, K=128) -----------
__global__ void __launch_bounds__(256) cls_kernel(
    const float* __restrict__ Wc, const float* __restrict__ bc,
    float* __restrict__ out, int M)
{
    __shared__ float Hs[16][128];
    __shared__ float Wcs[128][48];

    int tid  = threadIdx.x;
    int row0 = blockIdx.x * 16;

    for (int id = tid; id < 128 * NCLS; id += 256)
        Wcs[id / NCLS][id % NCLS] = Wc[id];

#pragma unroll
    for (int t = 0; t < 2; t++) {
        int id = tid + t * 256;
        int m  = id >> 5;
        int k4 = (id & 31) * 4;
        int row = row0 + m;
        float4 v = make_float4(0.f, 0.f, 0.f, 0.f);
        if (row < M) v = *(const float4*)(g_h + (size_t)row * 128 + k4);
        *(float4*)&Hs[m][k4] = v;
    }
    __syncthreads();

    int tx = tid & 63;
    int ty = tid >> 6;
    if (tx < NCLS) {
        float acc[4] = {0.f, 0.f, 0.f, 0.f};
#pragma unroll 4
        for (int k = 0; k < 128; k++) {
            float w = Wcs[k][tx];
#pragma unroll
            for (int i = 0; i < 4; i++)
                acc[i] = fmaf(Hs[ty * 4 + i][k], w, acc[i]);
        }
        float bias = bc[tx];
#pragma unroll
        for (int i = 0; i < 4; i++) {
            int row = row0 + ty * 4 + i;
            if (row < M) out[(size_t)row * NCLS + tx] = acc[i] + bias;
        }
    }
}

// ---------------- launch ----------------------------------------------------
extern "C" void kernel_launch(void* const* d_in, const int* in_sizes, int n_in,
                              void* d_out, int out_size)
{
    const float* x     = (const float*)d_in[0];
    const int*   edges = (const int*)  d_in[1];
    const float* W0    = (const float*)d_in[2];
    const float* b0    = (const float*)d_in[3];
    const float* W1    = (const float*)d_in[4];
    const float* b1    = (const float*)d_in[5];
    const float* Wc    = (const float*)d_in[6];
    const float* bc    = (const float*)d_in[7];
    float* out = (float*)d_out;

    const int nodeBlocks   = (N_NODES + 255) / 256;      // 391
    const int edgeBlocks   = (N_EDGES + 255) / 256;      // 6250
    const int gemmBlocks   = (N_NODES + 63) / 64;        // 1563
    const int gatherBlocks = (N_NODES + 7) / 8;          // 12500
    const int clsBlocks    = (N_NODES + 15) / 16;        // 6250

    // normalization coefficients + CSR build
    zero_counts_kernel<<<nodeBlocks, 256>>>();
    degree_kernel<<<edgeBlocks, 256>>>(edges);
    finish_deg_kernel<<<nodeBlocks, 256>>>();
    scan_kernel<<<1, 1024>>>();
    fill_csr_kernel<<<edgeBlocks, 256>>>(edges);

    // layer 0
    gemm128_kernel<<<gemmBlocks, 256>>>(x, 0, W0, N_NODES);
    gather_kernel<<<gatherBlocks, 256>>>(b0);

    // layer 1
    gemm128_kernel<<<gemmBlocks, 256>>>(nullptr, 1, W1, N_NODES);
    gather_kernel<<<gatherBlocks, 256>>>(b1);

    // classifier
    cls_kernel<<<clsBlocks, 256>>>(Wc, bc, out, N_NODES);
}

// round 6
// speedup vs baseline: 3.0430x; 1.4536x over previous
#include <cuda_runtime.h>

#define N_NODES 100000
#define N_EDGES 1600000
#define HID 128
#define NCLS 47
#define NBLK 391                                  // ceil(N_NODES/256)

// ---------------- scratch (static device globals; no runtime allocation) ----
__device__ float g_y  [(size_t)N_NODES * HID];   // GEMM output / gather source
__device__ float g_h  [(size_t)N_NODES * HID];   // post-activation hidden
__device__ float g_cs [N_NODES];                 // c_src = max(out_deg,1)^-0.5
__device__ float g_cd [N_NODES];                 // c_dst = max(in_deg,1)^-0.5
__device__ int   g_outdeg[N_NODES];
__device__ int   g_indeg [N_NODES];
__device__ int   g_cursor[N_NODES];
__device__ int   g_rowstart[N_NODES + 1];
__device__ int   g_csrc[N_EDGES];                // CSR: src ids grouped by dst
__device__ int   g_bsum[NBLK];                   // per-block indeg sums
__device__ int   g_boff[NBLK];                   // exclusive block offsets

// ---------------- degree / CSR pipeline ------------------------------------
__global__ void zero_counts_kernel() {
    int i = blockIdx.x * blockDim.x + threadIdx.x;
    if (i < N_NODES) { g_outdeg[i] = 0; g_indeg[i] = 0; g_cursor[i] = 0; }
}

__global__ void degree_kernel(const int* __restrict__ edges) {
    int i = blockIdx.x * blockDim.x + threadIdx.x;
    if (i < N_EDGES) {
        atomicAdd(&g_outdeg[edges[i]], 1);
        atomicAdd(&g_indeg [edges[N_EDGES + i]], 1);
    }
}

__global__ void finish_deg_kernel() {
    int i = blockIdx.x * blockDim.x + threadIdx.x;
    if (i < N_NODES) {
        g_cs[i] = rsqrtf(fmaxf((float)g_outdeg[i], 1.f));
        g_cd[i] = rsqrtf(fmaxf((float)g_indeg[i],  1.f));
    }
}

// ---- scan phase 1: per-block sums of g_indeg (256 elems/block) ------------
__global__ void __launch_bounds__(256) block_sum_kernel() {
    __shared__ int sm[8];
    int i = blockIdx.x * 256 + threadIdx.x;
    int v = (i < N_NODES) ? g_indeg[i] : 0;
#pragma unroll
    for (int off = 16; off > 0; off >>= 1)
        v += __shfl_down_sync(0xffffffffu, v, off);
    if ((threadIdx.x & 31) == 0) sm[threadIdx.x >> 5] = v;
    __syncthreads();
    if (threadIdx.x < 8) {
        int s = sm[threadIdx.x];
#pragma unroll
        for (int off = 4; off > 0; off >>= 1)
            s += __shfl_down_sync(0xffu, s, off);
        if (threadIdx.x == 0) g_bsum[blockIdx.x] = s;
    }
}

// ---- scan phase 2: exclusive scan of 391 block sums (one block) -----------
__global__ void __launch_bounds__(512) scan_bsum_kernel() {
    __shared__ int part[512];
    int t = threadIdx.x;
    part[t] = (t < NBLK) ? g_bsum[t] : 0;
    __syncthreads();
    for (int off = 1; off < 512; off <<= 1) {
        int v = (t >= off) ? part[t - off] : 0;
        __syncthreads();
        part[t] += v;
        __syncthreads();
    }
    if (t < NBLK) g_boff[t] = (t == 0) ? 0 : part[t - 1];
    if (t == 0) g_rowstart[N_NODES] = N_EDGES;
}

// ---- scan phase 3: local exclusive scan + block offset --> rowstart -------
__global__ void __launch_bounds__(256) rowstart_kernel() {
    __shared__ int part[256];
    int t = threadIdx.x;
    int i = blockIdx.x * 256 + t;
    int v = (i < N_NODES) ? g_indeg[i] : 0;
    part[t] = v;
    __syncthreads();
    for (int off = 1; off < 256; off <<= 1) {
        int u = (t >= off) ? part[t - off] : 0;
        __syncthreads();
        part[t] += u;
        __syncthreads();
    }
    if (i < N_NODES)
        g_rowstart[i] = g_boff[blockIdx.x] + part[t] - v;   // exclusive
}

__global__ void fill_csr_kernel(const int* __restrict__ edges) {
    int i = blockIdx.x * blockDim.x + threadIdx.x;
    if (i < N_EDGES) {
        int s = edges[i];
        int d = edges[N_EDGES + i];
        int pos = g_rowstart[d] + atomicAdd(&g_cursor[d], 1);
        g_csrc[pos] = s;
    }
}

// ---------------- main GEMM: Y = (A * c_src[:,None]) @ W  (K=N=128) --------
// Tile: 128 rows x 128 cols, BK=16. 256 threads, 8x8 register tile each.
__global__ void __launch_bounds__(256) gemm128_kernel(
    const float* __restrict__ X, int useH,
    const float* __restrict__ W, int M)
{
    const float* A = useH ? (const float*)g_h : X;

    __shared__ float As[16][132];  // [k][row], padded (132 % 4 == 0)
    __shared__ float Bs[16][128];  // [k][col]

    int tid  = threadIdx.x;
    int row0 = blockIdx.x * 128;
    int tix  = tid & 15;           // col group
    int tiy  = tid >> 4;           // row group

    float acc[8][8];
#pragma unroll
    for (int i = 0; i < 8; i++)
#pragma unroll
        for (int j = 0; j < 8; j++) acc[i][j] = 0.f;

    for (int k0 = 0; k0 < 128; k0 += 16) {
        // A chunk: 128 rows x 16 k = 512 float4 tasks, 2/thread; scale by c_src
#pragma unroll
        for (int t = 0; t < 2; t++) {
            int id   = tid + t * 256;
            int r    = id >> 2;            // 0..127
            int kk4  = (id & 3) * 4;       // 0,4,8,12
            int grow = row0 + r;
            float4 v = make_float4(0.f, 0.f, 0.f, 0.f);
            float  s = 0.f;
            if (grow < M) {
                v = *(const float4*)(A + (size_t)grow * 128 + k0 + kk4);
                s = g_cs[grow];
            }
            As[kk4 + 0][r] = v.x * s;
            As[kk4 + 1][r] = v.y * s;
            As[kk4 + 2][r] = v.z * s;
            As[kk4 + 3][r] = v.w * s;
        }
        // W chunk: 16 k x 128 cols = 512 float4 tasks, 2/thread
#pragma unroll
        for (int t = 0; t < 2; t++) {
            int id = tid + t * 256;
            int kk = id >> 5;              // 0..15
            int n4 = (id & 31) * 4;
            *(float4*)&Bs[kk][n4] = *(const float4*)(W + (size_t)(k0 + kk) * 128 + n4);
        }
        __syncthreads();

#pragma unroll
        for (int kk = 0; kk < 16; kk++) {
            float4 a0 = *(float4*)&As[kk][tiy * 4];
            float4 a1 = *(float4*)&As[kk][tiy * 4 + 64];
            float4 b0 = *(float4*)&Bs[kk][tix * 4];
            float4 b1 = *(float4*)&Bs[kk][tix * 4 + 64];
            float av[8] = {a0.x, a0.y, a0.z, a0.w, a1.x, a1.y, a1.z, a1.w};
            float bv[8] = {b0.x, b0.y, b0.z, b0.w, b1.x, b1.y, b1.z, b1.w};
#pragma unroll
            for (int i = 0; i < 8; i++)
#pragma unroll
                for (int j = 0; j < 8; j++)
                    acc[i][j] = fmaf(av[i], bv[j], acc[i][j]);
        }
        __syncthreads();
    }

    // write 8x8 tile: rows {tiy*4+i, tiy*4+64+i}, cols {tix*4.., tix*4+64..}
#pragma unroll
    for (int half = 0; half < 2; half++) {
#pragma unroll
        for (int i = 0; i < 4; i++) {
            int row = row0 + tiy * 4 + half * 64 + i;
            if (row < M) {
                int ai = half * 4 + i;
                float4 o0 = make_float4(acc[ai][0], acc[ai][1], acc[ai][2], acc[ai][3]);
                float4 o1 = make_float4(acc[ai][4], acc[ai][5], acc[ai][6], acc[ai][7]);
                *(float4*)(g_y + (size_t)row * 128 + tix * 4)      = o0;
                *(float4*)(g_y + (size_t)row * 128 + tix * 4 + 64) = o1;
            }
        }
    }
}

// ---------------- CSR gather + scale + bias + relu (fused) -----------------
// one warp per dst node; lane owns 4 consecutive feature floats.
__global__ void __launch_bounds__(256) gather_kernel(const float* __restrict__ b) {
    int w    = blockIdx.x * 8 + (threadIdx.x >> 5);
    int lane = threadIdx.x & 31;
    if (w >= N_NODES) return;

    int beg = __ldg(&g_rowstart[w]);
    int end = __ldg(&g_rowstart[w + 1]);

    float4 acc = make_float4(0.f, 0.f, 0.f, 0.f);

    for (int base = beg; base < end; base += 32) {
        int n   = end - base;
        int m   = n < 32 ? n : 32;
        int idx = (lane < m) ? __ldg(&g_csrc[base + lane]) : 0;

        int j = 0;
        for (; j + 4 <= m; j += 4) {
            int s0 = __shfl_sync(0xffffffffu, idx, j + 0);
            int s1 = __shfl_sync(0xffffffffu, idx, j + 1);
            int s2 = __shfl_sync(0xffffffffu, idx, j + 2);
            int s3 = __shfl_sync(0xffffffffu, idx, j + 3);
            float4 v0 = *(const float4*)(g_y + (size_t)s0 * 128 + lane * 4);
            float4 v1 = *(const float4*)(g_y + (size_t)s1 * 128 + lane * 4);
            float4 v2 = *(const float4*)(g_y + (size_t)s2 * 128 + lane * 4);
            float4 v3 = *(const float4*)(g_y + (size_t)s3 * 128 + lane * 4);
            acc.x += (v0.x + v1.x) + (v2.x + v3.x);
            acc.y += (v0.y + v1.y) + (v2.y + v3.y);
            acc.z += (v0.z + v1.z) + (v2.z + v3.z);
            acc.w += (v0.w + v1.w) + (v2.w + v3.w);
        }
        for (; j < m; j++) {
            int s = __shfl_sync(0xffffffffu, idx, j);
            float4 v = *(const float4*)(g_y + (size_t)s * 128 + lane * 4);
            acc.x += v.x; acc.y += v.y; acc.z += v.z; acc.w += v.w;
        }
    }

    float c = g_cd[w];
    float4 bb = *(const float4*)(b + lane * 4);
    float4 r;
    r.x = fmaxf(fmaf(acc.x, c, bb.x), 0.f);
    r.y = fmaxf(fmaf(acc.y, c, bb.y), 0.f);
    r.z = fmaxf(fmaf(acc.z, c, bb.z), 0.f);
    r.w = fmaxf(fmaf(acc.w, c, bb.w), 0.f);
    *(float4*)(g_h + (size_t)w * 128 + lane * 4) = r;
}

// ---------------- classifier: out = g_h @ Wc + bc  (N=47, K=128) -----------
__global__ void __launch_bounds__(256) cls_kernel(
    const float* __restrict__ Wc, const float* __restrict__ bc,
    float* __restrict__ out, int M)
{
    __shared__ float Hs[16][128];
    __shared__ float Wcs[128][48];

    int tid  = threadIdx.x;
    int row0 = blockIdx.x * 16;

    for (int id = tid; id < 128 * NCLS; id += 256)
        Wcs[id / NCLS][id % NCLS] = Wc[id];

#pragma unroll
    for (int t = 0; t < 2; t++) {
        int id = tid + t * 256;
        int m  = id >> 5;
        int k4 = (id & 31) * 4;
        int row = row0 + m;
        float4 v = make_float4(0.f, 0.f, 0.f, 0.f);
        if (row < M) v = *(const float4*)(g_h + (size_t)row * 128 + k4);
        *(float4*)&Hs[m][k4] = v;
    }
    __syncthreads();

    int tx = tid & 63;
    int ty = tid >> 6;
    if (tx < NCLS) {
        float acc[4] = {0.f, 0.f, 0.f, 0.f};
#pragma unroll 4
        for (int k = 0; k < 128; k++) {
            float w = Wcs[k][tx];
#pragma unroll
            for (int i = 0; i < 4; i++)
                acc[i] = fmaf(Hs[ty * 4 + i][k], w, acc[i]);
        }
        float bias = bc[tx];
#pragma unroll
        for (int i = 0; i < 4; i++) {
            int row = row0 + ty * 4 + i;
            if (row < M) out[(size_t)row * NCLS + tx] = acc[i] + bias;
        }
    }
}

// ---------------- launch ----------------------------------------------------
extern "C" void kernel_launch(void* const* d_in, const int* in_sizes, int n_in,
                              void* d_out, int out_size)
{
    const float* x     = (const float*)d_in[0];
    const int*   edges = (const int*)  d_in[1];
    const float* W0    = (const float*)d_in[2];
    const float* b0    = (const float*)d_in[3];
    const float* W1    = (const float*)d_in[4];
    const float* b1    = (const float*)d_in[5];
    const float* Wc    = (const float*)d_in[6];
    const float* bc    = (const float*)d_in[7];
    float* out = (float*)d_out;

    const int nodeBlocks   = (N_NODES + 255) / 256;      // 391
    const int edgeBlocks   = (N_EDGES + 255) / 256;      // 6250
    const int gemmBlocks   = (N_NODES + 127) / 128;      // 782
    const int gatherBlocks = (N_NODES + 7) / 8;          // 12500
    const int clsBlocks    = (N_NODES + 15) / 16;        // 6250

    // normalization coefficients + CSR build (parallel 3-phase scan)
    zero_counts_kernel<<<nodeBlocks, 256>>>();
    degree_kernel<<<edgeBlocks, 256>>>(edges);
    finish_deg_kernel<<<nodeBlocks, 256>>>();
    block_sum_kernel<<<NBLK, 256>>>();
    scan_bsum_kernel<<<1, 512>>>();
    rowstart_kernel<<<NBLK, 256>>>();
    fill_csr_kernel<<<edgeBlocks, 256>>>(edges);

    // layer 0
    gemm128_kernel<<<gemmBlocks, 256>>>(x, 0, W0, N_NODES);
    gather_kernel<<<gatherBlocks, 256>>>(b0);

    // layer 1
    gemm128_kernel<<<gemmBlocks, 256>>>(nullptr, 1, W1, N_NODES);
    gather_kernel<<<gatherBlocks, 256>>>(b1);

    // classifier
    cls_kernel<<<clsBlocks, 256>>>(Wc, bc, out, N_NODES);
}

// round 7
// speedup vs baseline: 3.3381x; 1.0970x over previous
#include <cuda_runtime.h>
#include <cuda_fp16.h>

#define N_NODES 100000
#define N_EDGES 1600000
#define HID 128
#define NCLS 47
#define NBLK 391                                  // ceil(N_NODES/256)

// ---------------- scratch (static device globals; no runtime allocation) ----
__device__ __half g_yh[(size_t)N_NODES * HID];   // GEMM output in fp16 (gather source)
__device__ float  g_h [(size_t)N_NODES * HID];   // post-activation hidden (fp32)
__device__ float  g_cs[N_NODES];                 // c_src = max(out_deg,1)^-0.5
__device__ float  g_cd[N_NODES];                 // c_dst = max(in_deg,1)^-0.5
__device__ int    g_outdeg[N_NODES];
__device__ int    g_indeg [N_NODES];
__device__ int    g_cursor[N_NODES];
__device__ int    g_rowstart[N_NODES + 1];
__device__ int    g_csrc[N_EDGES];               // CSR: src ids grouped by dst
__device__ int    g_bsum[NBLK];                  // per-block indeg sums
__device__ int    g_boff[NBLK];                  // exclusive block offsets

// ---------------- degree / CSR pipeline ------------------------------------
__global__ void zero_counts_kernel() {
    int i = blockIdx.x * blockDim.x + threadIdx.x;
    if (i < N_NODES) { g_outdeg[i] = 0; g_indeg[i] = 0; g_cursor[i] = 0; }
}

__global__ void degree_kernel(const int* __restrict__ edges) {
    int i = blockIdx.x * blockDim.x + threadIdx.x;
    if (i < N_EDGES) {
        atomicAdd(&g_outdeg[edges[i]], 1);
        atomicAdd(&g_indeg [edges[N_EDGES + i]], 1);
    }
}

__global__ void finish_deg_kernel() {
    int i = blockIdx.x * blockDim.x + threadIdx.x;
    if (i < N_NODES) {
        g_cs[i] = rsqrtf(fmaxf((float)g_outdeg[i], 1.f));
        g_cd[i] = rsqrtf(fmaxf((float)g_indeg[i],  1.f));
    }
}

// ---- scan phase 1: per-block sums of g_indeg (256 elems/block) ------------
__global__ void __launch_bounds__(256) block_sum_kernel() {
    __shared__ int sm[8];
    int i = blockIdx.x * 256 + threadIdx.x;
    int v = (i < N_NODES) ? g_indeg[i] : 0;
#pragma unroll
    for (int off = 16; off > 0; off >>= 1)
        v += __shfl_down_sync(0xffffffffu, v, off);
    if ((threadIdx.x & 31) == 0) sm[threadIdx.x >> 5] = v;
    __syncthreads();
    if (threadIdx.x < 8) {
        int s = sm[threadIdx.x];
#pragma unroll
        for (int off = 4; off > 0; off >>= 1)
            s += __shfl_down_sync(0xffu, s, off);
        if (threadIdx.x == 0) g_bsum[blockIdx.x] = s;
    }
}

// ---- scan phase 2: exclusive scan of 391 block sums (one block) -----------
__global__ void __launch_bounds__(512) scan_bsum_kernel() {
    __shared__ int part[512];
    int t = threadIdx.x;
    part[t] = (t < NBLK) ? g_bsum[t] : 0;
    __syncthreads();
    for (int off = 1; off < 512; off <<= 1) {
        int v = (t >= off) ? part[t - off] : 0;
        __syncthreads();
        part[t] += v;
        __syncthreads();
    }
    if (t < NBLK) g_boff[t] = (t == 0) ? 0 : part[t - 1];
    if (t == 0) g_rowstart[N_NODES] = N_EDGES;
}

// ---- scan phase 3: local exclusive scan + block offset --> rowstart -------
__global__ void __launch_bounds__(256) rowstart_kernel() {
    __shared__ int part[256];
    int t = threadIdx.x;
    int i = blockIdx.x * 256 + t;
    int v = (i < N_NODES) ? g_indeg[i] : 0;
    part[t] = v;
    __syncthreads();
    for (int off = 1; off < 256; off <<= 1) {
        int u = (t >= off) ? part[t - off] : 0;
        __syncthreads();
        part[t] += u;
        __syncthreads();
    }
    if (i < N_NODES)
        g_rowstart[i] = g_boff[blockIdx.x] + part[t] - v;   // exclusive
}

__global__ void fill_csr_kernel(const int* __restrict__ edges) {
    int i = blockIdx.x * blockDim.x + threadIdx.x;
    if (i < N_EDGES) {
        int s = edges[i];
        int d = edges[N_EDGES + i];
        int pos = g_rowstart[d] + atomicAdd(&g_cursor[d], 1);
        g_csrc[pos] = s;
    }
}

// ---------------- main GEMM: Yh = fp16((A * c_src[:,None]) @ W) ------------
// Tile: 128 rows x 128 cols, BK=16. 256 threads, 8x8 register tile each.
__global__ void __launch_bounds__(256) gemm128_kernel(
    const float* __restrict__ X, int useH,
    const float* __restrict__ W, int M)
{
    const float* A = useH ? (const float*)g_h : X;

    __shared__ float As[16][132];  // [k][row], padded
    __shared__ float Bs[16][128];  // [k][col]

    int tid  = threadIdx.x;
    int row0 = blockIdx.x * 128;
    int tix  = tid & 15;           // col group
    int tiy  = tid >> 4;           // row group

    float acc[8][8];
#pragma unroll
    for (int i = 0; i < 8; i++)
#pragma unroll
        for (int j = 0; j < 8; j++) acc[i][j] = 0.f;

    for (int k0 = 0; k0 < 128; k0 += 16) {
#pragma unroll
        for (int t = 0; t < 2; t++) {
            int id   = tid + t * 256;
            int r    = id >> 2;            // 0..127
            int kk4  = (id & 3) * 4;       // 0,4,8,12
            int grow = row0 + r;
            float4 v = make_float4(0.f, 0.f, 0.f, 0.f);
            float  s = 0.f;
            if (grow < M) {
                v = *(const float4*)(A + (size_t)grow * 128 + k0 + kk4);
                s = g_cs[grow];
            }
            As[kk4 + 0][r] = v.x * s;
            As[kk4 + 1][r] = v.y * s;
            As[kk4 + 2][r] = v.z * s;
            As[kk4 + 3][r] = v.w * s;
        }
#pragma unroll
        for (int t = 0; t < 2; t++) {
            int id = tid + t * 256;
            int kk = id >> 5;              // 0..15
            int n4 = (id & 31) * 4;
            *(float4*)&Bs[kk][n4] = *(const float4*)(W + (size_t)(k0 + kk) * 128 + n4);
        }
        __syncthreads();

#pragma unroll
        for (int kk = 0; kk < 16; kk++) {
            float4 a0 = *(float4*)&As[kk][tiy * 4];
            float4 a1 = *(float4*)&As[kk][tiy * 4 + 64];
            float4 b0 = *(float4*)&Bs[kk][tix * 4];
            float4 b1 = *(float4*)&Bs[kk][tix * 4 + 64];
            float av[8] = {a0.x, a0.y, a0.z, a0.w, a1.x, a1.y, a1.z, a1.w};
            float bv[8] = {b0.x, b0.y, b0.z, b0.w, b1.x, b1.y, b1.z, b1.w};
#pragma unroll
            for (int i = 0; i < 8; i++)
#pragma unroll
                for (int j = 0; j < 8; j++)
                    acc[i][j] = fmaf(av[i], bv[j], acc[i][j]);
        }
        __syncthreads();
    }

    // write 8x8 tile as fp16: rows {tiy*4+i, tiy*4+64+i}, cols {tix*4, tix*4+64}
#pragma unroll
    for (int half = 0; half < 2; half++) {
#pragma unroll
        for (int i = 0; i < 4; i++) {
            int row = row0 + tiy * 4 + half * 64 + i;
            if (row < M) {
                int ai = half * 4 + i;
                __half2 p0 = __floats2half2_rn(acc[ai][0], acc[ai][1]);
                __half2 p1 = __floats2half2_rn(acc[ai][2], acc[ai][3]);
                __half2 p2 = __floats2half2_rn(acc[ai][4], acc[ai][5]);
                __half2 p3 = __floats2half2_rn(acc[ai][6], acc[ai][7]);
                __half2* dst0 = (__half2*)(g_yh + (size_t)row * 128 + tix * 4);
                __half2* dst1 = (__half2*)(g_yh + (size_t)row * 128 + tix * 4 + 64);
                dst0[0] = p0; dst0[1] = p1;
                dst1[0] = p2; dst1[1] = p3;
            }
        }
    }
}

// ---------------- CSR gather (fp16 src) + scale + bias + relu --------------
// one warp per dst node; lane owns 4 consecutive feature values (8 bytes fp16).
__global__ void __launch_bounds__(256) gather_kernel(const float* __restrict__ b) {
    int w    = blockIdx.x * 8 + (threadIdx.x >> 5);
    int lane = threadIdx.x & 31;
    if (w >= N_NODES) return;

    int beg = __ldg(&g_rowstart[w]);
    int end = __ldg(&g_rowstart[w + 1]);

    float4 acc = make_float4(0.f, 0.f, 0.f, 0.f);

    for (int base = beg; base < end; base += 32) {
        int n   = end - base;
        int m   = n < 32 ? n : 32;
        int idx = (lane < m) ? __ldg(&g_csrc[base + lane]) : 0;

        int j = 0;
        for (; j + 4 <= m; j += 4) {
            int s0 = __shfl_sync(0xffffffffu, idx, j + 0);
            int s1 = __shfl_sync(0xffffffffu, idx, j + 1);
            int s2 = __shfl_sync(0xffffffffu, idx, j + 2);
            int s3 = __shfl_sync(0xffffffffu, idx, j + 3);
            uint2 r0 = *(const uint2*)(g_yh + (size_t)s0 * 128 + lane * 4);
            uint2 r1 = *(const uint2*)(g_yh + (size_t)s1 * 128 + lane * 4);
            uint2 r2 = *(const uint2*)(g_yh + (size_t)s2 * 128 + lane * 4);
            uint2 r3 = *(const uint2*)(g_yh + (size_t)s3 * 128 + lane * 4);
            float2 a0 = __half22float2(*(const __half2*)&r0.x);
            float2 b0_ = __half22float2(*(const __half2*)&r0.y);
            float2 a1 = __half22float2(*(const __half2*)&r1.x);
            float2 b1_ = __half22float2(*(const __half2*)&r1.y);
            float2 a2 = __half22float2(*(const __half2*)&r2.x);
            float2 b2_ = __half22float2(*(const __half2*)&r2.y);
            float2 a3 = __half22float2(*(const __half2*)&r3.x);
            float2 b3_ = __half22float2(*(const __half2*)&r3.y);
            acc.x += (a0.x + a1.x) + (a2.x + a3.x);
            acc.y += (a0.y + a1.y) + (a2.y + a3.y);
            acc.z += (b0_.x + b1_.x) + (b2_.x + b3_.x);
            acc.w += (b0_.y + b1_.y) + (b2_.y + b3_.y);
        }
        for (; j < m; j++) {
            int s = __shfl_sync(0xffffffffu, idx, j);
            uint2 r = *(const uint2*)(g_yh + (size_t)s * 128 + lane * 4);
            float2 a = __half22float2(*(const __half2*)&r.x);
            float2 c = __half22float2(*(const __half2*)&r.y);
            acc.x += a.x; acc.y += a.y; acc.z += c.x; acc.w += c.y;
        }
    }

    float c = g_cd[w];
    float4 bb = *(const float4*)(b + lane * 4);
    float4 r;
    r.x = fmaxf(fmaf(acc.x, c, bb.x), 0.f);
    r.y = fmaxf(fmaf(acc.y, c, bb.y), 0.f);
    r.z = fmaxf(fmaf(acc.z, c, bb.z), 0.f);
    r.w = fmaxf(fmaf(acc.w, c, bb.w), 0.f);
    *(float4*)(g_h + (size_t)w * 128 + lane * 4) = r;
}

// ---------------- classifier: out = g_h @ Wc + bc  (N=47, K=128) -----------
__global__ void __launch_bounds__(256) cls_kernel(
    const float* __restrict__ Wc, const float* __restrict__ bc,
    float* __restrict__ out, int M)
{
    __shared__ float Hs[16][128];
    __shared__ float Wcs[128][48];

    int tid  = threadIdx.x;
    int row0 = blockIdx.x * 16;

    for (int id = tid; id < 128 * NCLS; id += 256)
        Wcs[id / NCLS][id % NCLS] = Wc[id];

#pragma unroll
    for (int t = 0; t < 2; t++) {
        int id = tid + t * 256;
        int m  = id >> 5;
        int k4 = (id & 31) * 4;
        int row = row0 + m;
        float4 v = make_float4(0.f, 0.f, 0.f, 0.f);
        if (row < M) v = *(const float4*)(g_h + (size_t)row * 128 + k4);
        *(float4*)&Hs[m][k4] = v;
    }
    __syncthreads();

    int tx = tid & 63;
    int ty = tid >> 6;
    if (tx < NCLS) {
        float acc[4] = {0.f, 0.f, 0.f, 0.f};
#pragma unroll 4
        for (int k = 0; k < 128; k++) {
            float w = Wcs[k][tx];
#pragma unroll
            for (int i = 0; i < 4; i++)
                acc[i] = fmaf(Hs[ty * 4 + i][k], w, acc[i]);
        }
        float bias = bc[tx];
#pragma unroll
        for (int i = 0; i < 4; i++) {
            int row = row0 + ty * 4 + i;
            if (row < M) out[(size_t)row * NCLS + tx] = acc[i] + bias;
        }
    }
}

// ---------------- launch ----------------------------------------------------
extern "C" void kernel_launch(void* const* d_in, const int* in_sizes, int n_in,
                              void* d_out, int out_size)
{
    const float* x     = (const float*)d_in[0];
    const int*   edges = (const int*)  d_in[1];
    const float* W0    = (const float*)d_in[2];
    const float* b0    = (const float*)d_in[3];
    const float* W1    = (const float*)d_in[4];
    const float* b1    = (const float*)d_in[5];
    const float* Wc    = (const float*)d_in[6];
    const float* bc    = (const float*)d_in[7];
    float* out = (float*)d_out;

    const int nodeBlocks   = (N_NODES + 255) / 256;      // 391
    const int edgeBlocks   = (N_EDGES + 255) / 256;      // 6250
    const int gemmBlocks   = (N_NODES + 127) / 128;      // 782
    const int gatherBlocks = (N_NODES + 7) / 8;          // 12500
    const int clsBlocks    = (N_NODES + 15) / 16;        // 6250

    // normalization coefficients + CSR build (parallel 3-phase scan)
    zero_counts_kernel<<<nodeBlocks, 256>>>();
    degree_kernel<<<edgeBlocks, 256>>>(edges);
    finish_deg_kernel<<<nodeBlocks, 256>>>();
    block_sum_kernel<<<NBLK, 256>>>();
    scan_bsum_kernel<<<1, 512>>>();
    rowstart_kernel<<<NBLK, 256>>>();
    fill_csr_kernel<<<edgeBlocks, 256>>>(edges);

    // layer 0
    gemm128_kernel<<<gemmBlocks, 256>>>(x, 0, W0, N_NODES);
    gather_kernel<<<gatherBlocks, 256>>>(b0);

    // layer 1
    gemm128_kernel<<<gemmBlocks, 256>>>(nullptr, 1, W1, N_NODES);
    gather_kernel<<<gatherBlocks, 256>>>(b1);

    // classifier
    cls_kernel<<<clsBlocks, 256>>>(Wc, bc, out, N_NODES);
}

// round 8
// speedup vs baseline: 3.4932x; 1.0465x over previous
#include <cuda_runtime.h>
#include <cuda_fp16.h>
#include <cstdint>

#define N_NODES 100000
#define N_EDGES 1600000
#define HID 128
#define NCLS 47
#define NBLK 391                                  // ceil(N_NODES/256)

// ---------------- scratch (static device globals; no runtime allocation) ----
__device__ __half g_yh[(size_t)N_NODES * HID];   // GEMM output fp16 (gather source)
__device__ __half g_hh[(size_t)N_NODES * HID];   // post-activation hidden fp16
__device__ float  g_cs[N_NODES];                 // c_src = max(out_deg,1)^-0.5
__device__ float  g_cd[N_NODES];                 // c_dst = max(in_deg,1)^-0.5
__device__ int    g_outdeg[N_NODES];
__device__ int    g_indeg [N_NODES];
__device__ int    g_cursor[N_NODES];
__device__ int    g_rowstart[N_NODES + 1];
__device__ int    g_csrc[N_EDGES];               // CSR: src ids grouped by dst
__device__ int    g_bsum[NBLK];                  // per-block indeg sums
__device__ int    g_boff[NBLK];                  // exclusive block offsets

// ---------------- degree / CSR pipeline ------------------------------------
__global__ void zero_counts_kernel() {
    int i = blockIdx.x * blockDim.x + threadIdx.x;
    if (i < N_NODES) { g_outdeg[i] = 0; g_indeg[i] = 0; g_cursor[i] = 0; }
}

__global__ void degree_kernel(const int* __restrict__ edges) {
    int i = blockIdx.x * blockDim.x + threadIdx.x;
    if (i < N_EDGES) {
        atomicAdd(&g_outdeg[edges[i]], 1);
        atomicAdd(&g_indeg [edges[N_EDGES + i]], 1);
    }
}

__global__ void finish_deg_kernel() {
    int i = blockIdx.x * blockDim.x + threadIdx.x;
    if (i < N_NODES) {
        g_cs[i] = rsqrtf(fmaxf((float)g_outdeg[i], 1.f));
        g_cd[i] = rsqrtf(fmaxf((float)g_indeg[i],  1.f));
    }
}

// ---- scan phase 1: per-block sums of g_indeg (256 elems/block) ------------
__global__ void __launch_bounds__(256) block_sum_kernel() {
    __shared__ int sm[8];
    int i = blockIdx.x * 256 + threadIdx.x;
    int v = (i < N_NODES) ? g_indeg[i] : 0;
#pragma unroll
    for (int off = 16; off > 0; off >>= 1)
        v += __shfl_down_sync(0xffffffffu, v, off);
    if ((threadIdx.x & 31) == 0) sm[threadIdx.x >> 5] = v;
    __syncthreads();
    if (threadIdx.x < 8) {
        int s = sm[threadIdx.x];
#pragma unroll
        for (int off = 4; off > 0; off >>= 1)
            s += __shfl_down_sync(0xffu, s, off);
        if (threadIdx.x == 0) g_bsum[blockIdx.x] = s;
    }
}

// ---- scan phase 2: exclusive scan of 391 block sums (one block) -----------
__global__ void __launch_bounds__(512) scan_bsum_kernel() {
    __shared__ int part[512];
    int t = threadIdx.x;
    part[t] = (t < NBLK) ? g_bsum[t] : 0;
    __syncthreads();
    for (int off = 1; off < 512; off <<= 1) {
        int v = (t >= off) ? part[t - off] : 0;
        __syncthreads();
        part[t] += v;
        __syncthreads();
    }
    if (t < NBLK) g_boff[t] = (t == 0) ? 0 : part[t - 1];
    if (t == 0) g_rowstart[N_NODES] = N_EDGES;
}

// ---- scan phase 3: local exclusive scan + block offset --> rowstart -------
__global__ void __launch_bounds__(256) rowstart_kernel() {
    __shared__ int part[256];
    int t = threadIdx.x;
    int i = blockIdx.x * 256 + t;
    int v = (i < N_NODES) ? g_indeg[i] : 0;
    part[t] = v;
    __syncthreads();
    for (int off = 1; off < 256; off <<= 1) {
        int u = (t >= off) ? part[t - off] : 0;
        __syncthreads();
        part[t] += u;
        __syncthreads();
    }
    if (i < N_NODES)
        g_rowstart[i] = g_boff[blockIdx.x] + part[t] - v;   // exclusive
}

__global__ void fill_csr_kernel(const int* __restrict__ edges) {
    int i = blockIdx.x * blockDim.x + threadIdx.x;
    if (i < N_EDGES) {
        int s = edges[i];
        int d = edges[N_EDGES + i];
        int pos = g_rowstart[d] + atomicAdd(&g_cursor[d], 1);
        g_csrc[pos] = s;
    }
}

// ---------------- tensor-core GEMM: Yh = fp16((A*c_src) @ W) ---------------
// Block: 64 rows x 128 cols, K staged in 64-chunks. 8 warps (2x4), warp tile
// 32x32 via mma.sync.m16n8k16 (fp16 in, fp32 acc). A row-major, B as Bt[n][k]
// (= col-major B). Row pad +8 halves -> conflict-free fragment LDS.
__global__ void __launch_bounds__(256) gemm_mma_kernel(
    const float* __restrict__ X, int useH,
    const float* __restrict__ W, int M)
{
    __shared__ __align__(16) __half Ah[64][72];   // [m][k]
    __shared__ __align__(16) __half Bt[128][72];  // [n][k]

    int tid  = threadIdx.x;
    int lane = tid & 31;
    int warp = tid >> 5;
    int wm   = warp >> 2;     // 0..1
    int wn   = warp & 3;      // 0..3
    int g    = lane >> 2;     // 0..7 (group id)
    int tq   = lane & 3;      // 0..3

    int row0 = blockIdx.x * 64;

    float acc[2][4][4];
#pragma unroll
    for (int ma = 0; ma < 2; ma++)
#pragma unroll
        for (int na = 0; na < 4; na++)
#pragma unroll
            for (int q = 0; q < 4; q++) acc[ma][na][q] = 0.f;

    for (int k0 = 0; k0 < 128; k0 += 64) {
        // ---- stage A: 64 rows x 64 k, fp16, scaled by c_src ----
#pragma unroll
        for (int t = 0; t < 2; t++) {
            int id   = tid + t * 256;       // 0..511
            int r    = id >> 3;             // 0..63
            int kb   = (id & 7) * 8;        // 0..56 (8 halves/task)
            int grow = row0 + r;
            __half2 h[4];
            if (grow < M) {
                float s = g_cs[grow];
                if (!useH) {
                    const float4* p = (const float4*)(X + (size_t)grow * 128 + k0 + kb);
                    float4 v0 = p[0], v1 = p[1];
                    h[0] = __floats2half2_rn(v0.x * s, v0.y * s);
                    h[1] = __floats2half2_rn(v0.z * s, v0.w * s);
                    h[2] = __floats2half2_rn(v1.x * s, v1.y * s);
                    h[3] = __floats2half2_rn(v1.z * s, v1.w * s);
                } else {
                    uint4 u = *(const uint4*)(g_hh + (size_t)grow * 128 + k0 + kb);
                    const __half2* hp = (const __half2*)&u;
#pragma unroll
                    for (int q = 0; q < 4; q++) {
                        float2 f = __half22float2(hp[q]);
                        h[q] = __floats2half2_rn(f.x * s, f.y * s);
                    }
                }
            } else {
                __half2 z = __floats2half2_rn(0.f, 0.f);
                h[0] = z; h[1] = z; h[2] = z; h[3] = z;
            }
            uint4 st;
            st.x = *(uint32_t*)&h[0]; st.y = *(uint32_t*)&h[1];
            st.z = *(uint32_t*)&h[2]; st.w = *(uint32_t*)&h[3];
            *(uint4*)&Ah[r][kb] = st;
        }
        // ---- stage Bt: transpose W chunk [64 k x 128 n] -> [n][k] fp16 ----
#pragma unroll
        for (int t = 0; t < 8; t++) {
            int id = tid + t * 256;         // 0..2047
            int kk = id >> 5;               // 0..63
            int n4 = (id & 31) * 4;
            float4 w = *(const float4*)(W + (size_t)(k0 + kk) * 128 + n4);
            Bt[n4 + 0][kk] = __float2half_rn(w.x);
            Bt[n4 + 1][kk] = __float2half_rn(w.y);
            Bt[n4 + 2][kk] = __float2half_rn(w.z);
            Bt[n4 + 3][kk] = __float2half_rn(w.w);
        }
        __syncthreads();

        // ---- MMA over 4 k16 steps ----
#pragma unroll
        for (int ks = 0; ks < 64; ks += 16) {
            int kk = ks + tq * 2;
            uint32_t a[2][4], b[4][2];
#pragma unroll
            for (int ma = 0; ma < 2; ma++) {
                int r = wm * 32 + ma * 16 + g;
                a[ma][0] = *(const uint32_t*)&Ah[r][kk];
                a[ma][1] = *(const uint32_t*)&Ah[r + 8][kk];
                a[ma][2] = *(const uint32_t*)&Ah[r][kk + 8];
                a[ma][3] = *(const uint32_t*)&Ah[r + 8][kk + 8];
            }
#pragma unroll
            for (int na = 0; na < 4; na++) {
                int c = wn * 32 + na * 8 + g;
                b[na][0] = *(const uint32_t*)&Bt[c][kk];
                b[na][1] = *(const uint32_t*)&Bt[c][kk + 8];
            }
#pragma unroll
            for (int ma = 0; ma < 2; ma++)
#pragma unroll
                for (int na = 0; na < 4; na++) {
                    asm volatile(
                        "mma.sync.aligned.m16n8k16.row.col.f32.f16.f16.f32 "
                        "{%0,%1,%2,%3}, {%4,%5,%6,%7}, {%8,%9}, {%0,%1,%2,%3};\n"
                        : "+f"(acc[ma][na][0]), "+f"(acc[ma][na][1]),
                          "+f"(acc[ma][na][2]), "+f"(acc[ma][na][3])
                        : "r"(a[ma][0]), "r"(a[ma][1]), "r"(a[ma][2]), "r"(a[ma][3]),
                          "r"(b[na][0]), "r"(b[na][1]));
                }
        }
        __syncthreads();
    }

    // ---- epilogue: fp32 acc -> fp16 g_yh ----
#pragma unroll
    for (int ma = 0; ma < 2; ma++) {
        int r0 = row0 + wm * 32 + ma * 16 + g;
        int r1 = r0 + 8;
#pragma unroll
        for (int na = 0; na < 4; na++) {
            int col = wn * 32 + na * 8 + tq * 2;
            if (r0 < M)
                *(__half2*)(g_yh + (size_t)r0 * 128 + col) =
                    __floats2half2_rn(acc[ma][na][0], acc[ma][na][1]);
            if (r1 < M)
                *(__half2*)(g_yh + (size_t)r1 * 128 + col) =
                    __floats2half2_rn(acc[ma][na][2], acc[ma][na][3]);
        }
    }
}

// ---------------- CSR gather (fp16 src) + scale + bias + relu -> fp16 ------
// one warp per dst node; lane owns 4 consecutive feature values (8 bytes fp16).
__global__ void __launch_bounds__(256) gather_kernel(const float* __restrict__ b) {
    int w    = blockIdx.x * 8 + (threadIdx.x >> 5);
    int lane = threadIdx.x & 31;
    if (w >= N_NODES) return;

    int beg = __ldg(&g_rowstart[w]);
    int end = __ldg(&g_rowstart[w + 1]);

    float4 acc = make_float4(0.f, 0.f, 0.f, 0.f);

    for (int base = beg; base < end; base += 32) {
        int n   = end - base;
        int m   = n < 32 ? n : 32;
        int idx = (lane < m) ? __ldg(&g_csrc[base + lane]) : 0;

        int j = 0;
        for (; j + 4 <= m; j += 4) {
            int s0 = __shfl_sync(0xffffffffu, idx, j + 0);
            int s1 = __shfl_sync(0xffffffffu, idx, j + 1);
            int s2 = __shfl_sync(0xffffffffu, idx, j + 2);
            int s3 = __shfl_sync(0xffffffffu, idx, j + 3);
            uint2 r0 = *(const uint2*)(g_yh + (size_t)s0 * 128 + lane * 4);
            uint2 r1 = *(const uint2*)(g_yh + (size_t)s1 * 128 + lane * 4);
            uint2 r2 = *(const uint2*)(g_yh + (size_t)s2 * 128 + lane * 4);
            uint2 r3 = *(const uint2*)(g_yh + (size_t)s3 * 128 + lane * 4);
            float2 a0 = __half22float2(*(const __half2*)&r0.x);
            float2 b0_ = __half22float2(*(const __half2*)&r0.y);
            float2 a1 = __half22float2(*(const __half2*)&r1.x);
            float2 b1_ = __half22float2(*(const __half2*)&r1.y);
            float2 a2 = __half22float2(*(const __half2*)&r2.x);
            float2 b2_ = __half22float2(*(const __half2*)&r2.y);
            float2 a3 = __half22float2(*(const __half2*)&r3.x);
            float2 b3_ = __half22float2(*(const __half2*)&r3.y);
            acc.x += (a0.x + a1.x) + (a2.x + a3.x);
            acc.y += (a0.y + a1.y) + (a2.y + a3.y);
            acc.z += (b0_.x + b1_.x) + (b2_.x + b3_.x);
            acc.w += (b0_.y + b1_.y) + (b2_.y + b3_.y);
        }
        for (; j < m; j++) {
            int s = __shfl_sync(0xffffffffu, idx, j);
            uint2 r = *(const uint2*)(g_yh + (size_t)s * 128 + lane * 4);
            float2 a = __half22float2(*(const __half2*)&r.x);
            float2 c = __half22float2(*(const __half2*)&r.y);
            acc.x += a.x; acc.y += a.y; acc.z += c.x; acc.w += c.y;
        }
    }

    float c = g_cd[w];
    float4 bb = *(const float4*)(b + lane * 4);
    __half2 o0 = __floats2half2_rn(fmaxf(fmaf(acc.x, c, bb.x), 0.f),
                                   fmaxf(fmaf(acc.y, c, bb.y), 0.f));
    __half2 o1 = __floats2half2_rn(fmaxf(fmaf(acc.z, c, bb.z), 0.f),
                                   fmaxf(fmaf(acc.w, c, bb.w), 0.f));
    uint2 pack;
    pack.x = *(uint32_t*)&o0;
    pack.y = *(uint32_t*)&o1;
    *(uint2*)(g_hh + (size_t)w * 128 + lane * 4) = pack;
}

// ---------------- classifier: out = g_hh @ Wc + bc  (N=47, K=128) ----------
__global__ void __launch_bounds__(256) cls_kernel(
    const float* __restrict__ Wc, const float* __restrict__ bc,
    float* __restrict__ out, int M)
{
    __shared__ float Hs[16][128];
    __shared__ float Wcs[128][48];

    int tid  = threadIdx.x;
    int row0 = blockIdx.x * 16;

    for (int id = tid; id < 128 * NCLS; id += 256)
        Wcs[id / NCLS][id % NCLS] = Wc[id];

#pragma unroll
    for (int t = 0; t < 2; t++) {
        int id = tid + t * 256;
        int m  = id >> 5;
        int k4 = (id & 31) * 4;
        int row = row0 + m;
        float4 v = make_float4(0.f, 0.f, 0.f, 0.f);
        if (row < M) {
            uint2 u = *(const uint2*)(g_hh + (size_t)row * 128 + k4);
            float2 f0 = __half22float2(*(const __half2*)&u.x);
            float2 f1 = __half22float2(*(const __half2*)&u.y);
            v = make_float4(f0.x, f0.y, f1.x, f1.y);
        }
        *(float4*)&Hs[m][k4] = v;
    }
    __syncthreads();

    int tx = tid & 63;
    int ty = tid >> 6;
    if (tx < NCLS) {
        float acc[4] = {0.f, 0.f, 0.f, 0.f};
#pragma unroll 4
        for (int k = 0; k < 128; k++) {
            float w = Wcs[k][tx];
#pragma unroll
            for (int i = 0; i < 4; i++)
                acc[i] = fmaf(Hs[ty * 4 + i][k], w, acc[i]);
        }
        float bias = bc[tx];
#pragma unroll
        for (int i = 0; i < 4; i++) {
            int row = row0 + ty * 4 + i;
            if (row < M) out[(size_t)row * NCLS + tx] = acc[i] + bias;
        }
    }
}

// ---------------- launch ----------------------------------------------------
extern "C" void kernel_launch(void* const* d_in, const int* in_sizes, int n_in,
                              void* d_out, int out_size)
{
    const float* x     = (const float*)d_in[0];
    const int*   edges = (const int*)  d_in[1];
    const float* W0    = (const float*)d_in[2];
    const float* b0    = (const float*)d_in[3];
    const float* W1    = (const float*)d_in[4];
    const float* b1    = (const float*)d_in[5];
    const float* Wc    = (const float*)d_in[6];
    const float* bc    = (const float*)d_in[7];
    float* out = (float*)d_out;

    const int nodeBlocks   = (N_NODES + 255) / 256;      // 391
    const int edgeBlocks   = (N_EDGES + 255) / 256;      // 6250
    const int gemmBlocks   = (N_NODES + 63) / 64;        // 1563
    const int gatherBlocks = (N_NODES + 7) / 8;          // 12500
    const int clsBlocks    = (N_NODES + 15) / 16;        // 6250

    // normalization coefficients + CSR build (parallel 3-phase scan)
    zero_counts_kernel<<<nodeBlocks, 256>>>();
    degree_kernel<<<edgeBlocks, 256>>>(edges);
    finish_deg_kernel<<<nodeBlocks, 256>>>();
    block_sum_kernel<<<NBLK, 256>>>();
    scan_bsum_kernel<<<1, 512>>>();
    rowstart_kernel<<<NBLK, 256>>>();
    fill_csr_kernel<<<edgeBlocks, 256>>>(edges);

    // layer 0
    gemm_mma_kernel<<<gemmBlocks, 256>>>(x, 0, W0, N_NODES);
    gather_kernel<<<gatherBlocks, 256>>>(b0);

    // layer 1
    gemm_mma_kernel<<<gemmBlocks, 256>>>(nullptr, 1, W1, N_NODES);
    gather_kernel<<<gatherBlocks, 256>>>(b1);

    // classifier
    cls_kernel<<<clsBlocks, 256>>>(Wc, bc, out, N_NODES);
}

// round 9
// speedup vs baseline: 4.4044x; 1.2609x over previous
#include <cuda_runtime.h>
#include <cuda_fp16.h>
#include <cstdint>

#define N_NODES 100000
#define N_EDGES 1600000
#define HID 128
#define NCLS 47
#define NBLK 391                                  // ceil(N_NODES/256)

// ---------------- scratch (static device globals; no runtime allocation) ----
__device__ __half g_yh[(size_t)N_NODES * HID];   // GEMM output fp16 (gather source)
__device__ __half g_hh[(size_t)N_NODES * HID];   // post-activation hidden fp16
__device__ __half g_wt0[HID * HID];              // W0^T fp16  [n][k]
__device__ __half g_wt1[HID * HID];              // W1^T fp16  [n][k]
__device__ float  g_cs[N_NODES];
__device__ float  g_cd[N_NODES];
__device__ int    g_outdeg[N_NODES];
__device__ int    g_indeg [N_NODES];
__device__ int    g_cursor[N_NODES];
__device__ int    g_rowstart[N_NODES + 1];
__device__ int    g_csrc[N_EDGES];
__device__ int    g_bsum[NBLK];
__device__ int    g_boff[NBLK];

// ---------------- degree / CSR pipeline ------------------------------------
__global__ void zero_counts_kernel() {
    int i = blockIdx.x * blockDim.x + threadIdx.x;
    if (i < N_NODES) { g_outdeg[i] = 0; g_indeg[i] = 0; g_cursor[i] = 0; }
}

__global__ void degree_kernel(const int* __restrict__ edges) {
    int i = blockIdx.x * blockDim.x + threadIdx.x;
    if (i < N_EDGES) {
        atomicAdd(&g_outdeg[edges[i]], 1);
        atomicAdd(&g_indeg [edges[N_EDGES + i]], 1);
    }
}

__global__ void finish_deg_kernel() {
    int i = blockIdx.x * blockDim.x + threadIdx.x;
    if (i < N_NODES) {
        g_cs[i] = rsqrtf(fmaxf((float)g_outdeg[i], 1.f));
        g_cd[i] = rsqrtf(fmaxf((float)g_indeg[i],  1.f));
    }
}

// ---- W pre-transpose + fp16 convert (both layers), 16384 elems each -------
__global__ void prep_w_kernel(const float* __restrict__ W0,
                              const float* __restrict__ W1) {
    int idx = blockIdx.x * 256 + threadIdx.x;
    if (idx < HID * HID) {
        int n = idx >> 7, k = idx & 127;
        g_wt0[idx] = __float2half_rn(W0[k * 128 + n]);
        g_wt1[idx] = __float2half_rn(W1[k * 128 + n]);
    }
}

// ---- scan phase 1 ----------------------------------------------------------
__global__ void __launch_bounds__(256) block_sum_kernel() {
    __shared__ int sm[8];
    int i = blockIdx.x * 256 + threadIdx.x;
    int v = (i < N_NODES) ? g_indeg[i] : 0;
#pragma unroll
    for (int off = 16; off > 0; off >>= 1)
        v += __shfl_down_sync(0xffffffffu, v, off);
    if ((threadIdx.x & 31) == 0) sm[threadIdx.x >> 5] = v;
    __syncthreads();
    if (threadIdx.x < 8) {
        int s = sm[threadIdx.x];
#pragma unroll
        for (int off = 4; off > 0; off >>= 1)
            s += __shfl_down_sync(0xffu, s, off);
        if (threadIdx.x == 0) g_bsum[blockIdx.x] = s;
    }
}

// ---- scan phase 2 ----------------------------------------------------------
__global__ void __launch_bounds__(512) scan_bsum_kernel() {
    __shared__ int part[512];
    int t = threadIdx.x;
    part[t] = (t < NBLK) ? g_bsum[t] : 0;
    __syncthreads();
    for (int off = 1; off < 512; off <<= 1) {
        int v = (t >= off) ? part[t - off] : 0;
        __syncthreads();
        part[t] += v;
        __syncthreads();
    }
    if (t < NBLK) g_boff[t] = (t == 0) ? 0 : part[t - 1];
    if (t == 0) g_rowstart[N_NODES] = N_EDGES;
}

// ---- scan phase 3 ----------------------------------------------------------
__global__ void __launch_bounds__(256) rowstart_kernel() {
    __shared__ int part[256];
    int t = threadIdx.x;
    int i = blockIdx.x * 256 + t;
    int v = (i < N_NODES) ? g_indeg[i] : 0;
    part[t] = v;
    __syncthreads();
    for (int off = 1; off < 256; off <<= 1) {
        int u = (t >= off) ? part[t - off] : 0;
        __syncthreads();
        part[t] += u;
        __syncthreads();
    }
    if (i < N_NODES)
        g_rowstart[i] = g_boff[blockIdx.x] + part[t] - v;
}

__global__ void fill_csr_kernel(const int* __restrict__ edges) {
    int i = blockIdx.x * blockDim.x + threadIdx.x;
    if (i < N_EDGES) {
        int s = edges[i];
        int d = edges[N_EDGES + i];
        int pos = g_rowstart[d] + atomicAdd(&g_cursor[d], 1);
        g_csrc[pos] = s;
    }
}

// ---------------- tensor-core GEMM: Yh = fp16((A*c_src) @ W) ---------------
// Block 64x128, K chunked x64. 8 warps (2x4), warp tile 32x32,
// mma.m16n8k16 fp16->fp32. Fragments via ldmatrix (stride 72 halves = 9
// 16B-chunks -> conflict-free LDSM). W pre-transposed fp16 in g_wt*.
__global__ void __launch_bounds__(256) gemm_mma_kernel(
    const float* __restrict__ X, int layer, int M)
{
    __shared__ __align__(16) __half Ah[64][72];
    __shared__ __align__(16) __half Bt[128][72];

    const __half* Wt = layer ? g_wt1 : g_wt0;

    int tid  = threadIdx.x;
    int lane = tid & 31;
    int warp = tid >> 5;
    int wm   = warp >> 2;     // 0..1
    int wn   = warp & 3;      // 0..3
    int g    = lane >> 2;     // 0..7
    int tq   = lane & 3;      // 0..3
    int row0 = blockIdx.x * 64;

    // ldmatrix lane addressing (byte offsets within padded tiles)
    uint32_t ahBase = (uint32_t)__cvta_generic_to_shared(&Ah[0][0]);
    uint32_t btBase = (uint32_t)__cvta_generic_to_shared(&Bt[0][0]);
    int atrow = lane & 15;
    int athalf = (lane >> 4) * 8;
    uint32_t aAddr[2];
#pragma unroll
    for (int ma = 0; ma < 2; ma++)
        aAddr[ma] = ahBase + ((wm * 32 + ma * 16 + atrow) * 72 + athalf) * 2;
    int btrow = (lane & 7) + ((lane >> 4) << 3);
    int bthalf = ((lane >> 3) & 1) * 8;
    uint32_t bAddr[2];
#pragma unroll
    for (int p = 0; p < 2; p++)
        bAddr[p] = btBase + ((wn * 32 + p * 16 + btrow) * 72 + bthalf) * 2;

    float acc[2][4][4];
#pragma unroll
    for (int ma = 0; ma < 2; ma++)
#pragma unroll
        for (int na = 0; na < 4; na++)
#pragma unroll
            for (int q = 0; q < 4; q++) acc[ma][na][q] = 0.f;

    for (int k0 = 0; k0 < 128; k0 += 64) {
        // ---- stage A: 64 rows x 64 halves, scaled by c_src ----
#pragma unroll
        for (int t = 0; t < 2; t++) {
            int id   = tid + t * 256;       // 0..511
            int r    = id >> 3;             // 0..63
            int kb   = (id & 7) * 8;        // 0..56
            int grow = row0 + r;
            __half2 h[4];
            if (grow < M) {
                float s = g_cs[grow];
                if (!layer) {
                    const float4* p = (const float4*)(X + (size_t)grow * 128 + k0 + kb);
                    float4 v0 = p[0], v1 = p[1];
                    h[0] = __floats2half2_rn(v0.x * s, v0.y * s);
                    h[1] = __floats2half2_rn(v0.z * s, v0.w * s);
                    h[2] = __floats2half2_rn(v1.x * s, v1.y * s);
                    h[3] = __floats2half2_rn(v1.z * s, v1.w * s);
                } else {
                    uint4 u = *(const uint4*)(g_hh + (size_t)grow * 128 + k0 + kb);
                    const __half2* hp = (const __half2*)&u;
#pragma unroll
                    for (int q = 0; q < 4; q++) {
                        float2 f = __half22float2(hp[q]);
                        h[q] = __floats2half2_rn(f.x * s, f.y * s);
                    }
                }
            } else {
                __half2 z = __floats2half2_rn(0.f, 0.f);
                h[0] = z; h[1] = z; h[2] = z; h[3] = z;
            }
            uint4 st;
            st.x = *(uint32_t*)&h[0]; st.y = *(uint32_t*)&h[1];
            st.z = *(uint32_t*)&h[2]; st.w = *(uint32_t*)&h[3];
            *(uint4*)&Ah[r][kb] = st;
        }
        // ---- stage Bt: vectorized copy of pre-transposed fp16 W ----
#pragma unroll
        for (int t = 0; t < 4; t++) {
            int id = tid + t * 256;         // 0..1023
            int n  = id >> 3;               // 0..127
            int kb = (id & 7) * 8;          // 0..56
            *(uint4*)&Bt[n][kb] = *(const uint4*)(Wt + (size_t)n * 128 + k0 + kb);
        }
        __syncthreads();

        // ---- MMA over 4 k16 steps, fragments via ldmatrix ----
#pragma unroll
        for (int ks = 0; ks < 64; ks += 16) {
            uint32_t a[2][4], b[4][2];
#pragma unroll
            for (int ma = 0; ma < 2; ma++) {
                asm volatile(
                    "ldmatrix.sync.aligned.m8n8.x4.shared.b16 {%0,%1,%2,%3}, [%4];\n"
                    : "=r"(a[ma][0]), "=r"(a[ma][1]), "=r"(a[ma][2]), "=r"(a[ma][3])
                    : "r"(aAddr[ma] + ks * 2));
            }
#pragma unroll
            for (int p = 0; p < 2; p++) {
                uint32_t r0, r1, r2, r3;
                asm volatile(
                    "ldmatrix.sync.aligned.m8n8.x4.shared.b16 {%0,%1,%2,%3}, [%4];\n"
                    : "=r"(r0), "=r"(r1), "=r"(r2), "=r"(r3)
                    : "r"(bAddr[p] + ks * 2));
                b[p * 2 + 0][0] = r0; b[p * 2 + 0][1] = r1;
                b[p * 2 + 1][0] = r2; b[p * 2 + 1][1] = r3;
            }
#pragma unroll
            for (int ma = 0; ma < 2; ma++)
#pragma unroll
                for (int na = 0; na < 4; na++) {
                    asm volatile(
                        "mma.sync.aligned.m16n8k16.row.col.f32.f16.f16.f32 "
                        "{%0,%1,%2,%3}, {%4,%5,%6,%7}, {%8,%9}, {%0,%1,%2,%3};\n"
                        : "+f"(acc[ma][na][0]), "+f"(acc[ma][na][1]),
                          "+f"(acc[ma][na][2]), "+f"(acc[ma][na][3])
                        : "r"(a[ma][0]), "r"(a[ma][1]), "r"(a[ma][2]), "r"(a[ma][3]),
                          "r"(b[na][0]), "r"(b[na][1]));
                }
        }
        __syncthreads();
    }

    // ---- epilogue: fp32 acc -> fp16 g_yh ----
#pragma unroll
    for (int ma = 0; ma < 2; ma++) {
        int r0 = row0 + wm * 32 + ma * 16 + g;
        int r1 = r0 + 8;
#pragma unroll
        for (int na = 0; na < 4; na++) {
            int col = wn * 32 + na * 8 + tq * 2;
            if (r0 < M)
                *(__half2*)(g_yh + (size_t)r0 * 128 + col) =
                    __floats2half2_rn(acc[ma][na][0], acc[ma][na][1]);
            if (r1 < M)
                *(__half2*)(g_yh + (size_t)r1 * 128 + col) =
                    __floats2half2_rn(acc[ma][na][2], acc[ma][na][3]);
        }
    }
}

// ---------------- CSR gather (fp16 src) + scale + bias + relu -> fp16 ------
__global__ void __launch_bounds__(256) gather_kernel(const float* __restrict__ b) {
    int w    = blockIdx.x * 8 + (threadIdx.x >> 5);
    int lane = threadIdx.x & 31;
    if (w >= N_NODES) return;

    int beg = __ldg(&g_rowstart[w]);
    int end = __ldg(&g_rowstart[w + 1]);

    float4 acc = make_float4(0.f, 0.f, 0.f, 0.f);

    for (int base = beg; base < end; base += 32) {
        int n   = end - base;
        int m   = n < 32 ? n : 32;
        int idx = (lane < m) ? __ldg(&g_csrc[base + lane]) : 0;

        int j = 0;
        for (; j + 4 <= m; j += 4) {
            int s0 = __shfl_sync(0xffffffffu, idx, j + 0);
            int s1 = __shfl_sync(0xffffffffu, idx, j + 1);
            int s2 = __shfl_sync(0xffffffffu, idx, j + 2);
            int s3 = __shfl_sync(0xffffffffu, idx, j + 3);
            uint2 r0 = *(const uint2*)(g_yh + (size_t)s0 * 128 + lane * 4);
            uint2 r1 = *(const uint2*)(g_yh + (size_t)s1 * 128 + lane * 4);
            uint2 r2 = *(const uint2*)(g_yh + (size_t)s2 * 128 + lane * 4);
            uint2 r3 = *(const uint2*)(g_yh + (size_t)s3 * 128 + lane * 4);
            float2 a0 = __half22float2(*(const __half2*)&r0.x);
            float2 b0_ = __half22float2(*(const __half2*)&r0.y);
            float2 a1 = __half22float2(*(const __half2*)&r1.x);
            float2 b1_ = __half22float2(*(const __half2*)&r1.y);
            float2 a2 = __half22float2(*(const __half2*)&r2.x);
            float2 b2_ = __half22float2(*(const __half2*)&r2.y);
            float2 a3 = __half22float2(*(const __half2*)&r3.x);
            float2 b3_ = __half22float2(*(const __half2*)&r3.y);
            acc.x += (a0.x + a1.x) + (a2.x + a3.x);
            acc.y += (a0.y + a1.y) + (a2.y + a3.y);
            acc.z += (b0_.x + b1_.x) + (b2_.x + b3_.x);
            acc.w += (b0_.y + b1_.y) + (b2_.y + b3_.y);
        }
        for (; j < m; j++) {
            int s = __shfl_sync(0xffffffffu, idx, j);
            uint2 r = *(const uint2*)(g_yh + (size_t)s * 128 + lane * 4);
            float2 a = __half22float2(*(const __half2*)&r.x);
            float2 c = __half22float2(*(const __half2*)&r.y);
            acc.x += a.x; acc.y += a.y; acc.z += c.x; acc.w += c.y;
        }
    }

    float c = g_cd[w];
    float4 bb = *(const float4*)(b + lane * 4);
    __half2 o0 = __floats2half2_rn(fmaxf(fmaf(acc.x, c, bb.x), 0.f),
                                   fmaxf(fmaf(acc.y, c, bb.y), 0.f));
    __half2 o1 = __floats2half2_rn(fmaxf(fmaf(acc.z, c, bb.z), 0.f),
                                   fmaxf(fmaf(acc.w, c, bb.w), 0.f));
    uint2 pack;
    pack.x = *(uint32_t*)&o0;
    pack.y = *(uint32_t*)&o1;
    *(uint2*)(g_hh + (size_t)w * 128 + lane * 4) = pack;
}

// ---------------- classifier: out = g_hh @ Wc + bc  (N=47, K=128) ----------
__global__ void __launch_bounds__(256) cls_kernel(
    const float* __restrict__ Wc, const float* __restrict__ bc,
    float* __restrict__ out, int M)
{
    __shared__ float Hs[16][128];
    __shared__ float Wcs[128][48];

    int tid  = threadIdx.x;
    int row0 = blockIdx.x * 16;

    for (int id = tid; id < 128 * NCLS; id += 256)
        Wcs[id / NCLS][id % NCLS] = Wc[id];

#pragma unroll
    for (int t = 0; t < 2; t++) {
        int id = tid + t * 256;
        int m  = id >> 5;
        int k4 = (id & 31) * 4;
        int row = row0 + m;
        float4 v = make_float4(0.f, 0.f, 0.f, 0.f);
        if (row < M) {
            uint2 u = *(const uint2*)(g_hh + (size_t)row * 128 + k4);
            float2 f0 = __half22float2(*(const __half2*)&u.x);
            float2 f1 = __half22float2(*(const __half2*)&u.y);
            v = make_float4(f0.x, f0.y, f1.x, f1.y);
        }
        *(float4*)&Hs[m][k4] = v;
    }
    __syncthreads();

    int tx = tid & 63;
    int ty = tid >> 6;
    if (tx < NCLS) {
        float acc[4] = {0.f, 0.f, 0.f, 0.f};
#pragma unroll 4
        for (int k = 0; k < 128; k++) {
            float w = Wcs[k][tx];
#pragma unroll
            for (int i = 0; i < 4; i++)
                acc[i] = fmaf(Hs[ty * 4 + i][k], w, acc[i]);
        }
        float bias = bc[tx];
#pragma unroll
        for (int i = 0; i < 4; i++) {
            int row = row0 + ty * 4 + i;
            if (row < M) out[(size_t)row * NCLS + tx] = acc[i] + bias;
        }
    }
}

// ---------------- launch ----------------------------------------------------
extern "C" void kernel_launch(void* const* d_in, const int* in_sizes, int n_in,
                              void* d_out, int out_size)
{
    const float* x     = (const float*)d_in[0];
    const int*   edges = (const int*)  d_in[1];
    const float* W0    = (const float*)d_in[2];
    const float* b0    = (const float*)d_in[3];
    const float* W1    = (const float*)d_in[4];
    const float* b1    = (const float*)d_in[5];
    const float* Wc    = (const float*)d_in[6];
    const float* bc    = (const float*)d_in[7];
    float* out = (float*)d_out;

    const int nodeBlocks   = (N_NODES + 255) / 256;      // 391
    const int edgeBlocks   = (N_EDGES + 255) / 256;      // 6250
    const int gemmBlocks   = (N_NODES + 63) / 64;        // 1563
    const int gatherBlocks = (N_NODES + 7) / 8;          // 12500
    const int clsBlocks    = (N_NODES + 15) / 16;        // 6250

    // normalization coefficients + CSR build + weight prep
    zero_counts_kernel<<<nodeBlocks, 256>>>();
    degree_kernel<<<edgeBlocks, 256>>>(edges);
    prep_w_kernel<<<64, 256>>>(W0, W1);
    finish_deg_kernel<<<nodeBlocks, 256>>>();
    block_sum_kernel<<<NBLK, 256>>>();
    scan_bsum_kernel<<<1, 512>>>();
    rowstart_kernel<<<NBLK, 256>>>();
    fill_csr_kernel<<<edgeBlocks, 256>>>(edges);

    // layer 0
    gemm_mma_kernel<<<gemmBlocks, 256>>>(x, 0, N_NODES);
    gather_kernel<<<gatherBlocks, 256>>>(b0);

    // layer 1
    gemm_mma_kernel<<<gemmBlocks, 256>>>(nullptr, 1, N_NODES);
    gather_kernel<<<gatherBlocks, 256>>>(b1);

    // classifier
    cls_kernel<<<clsBlocks, 256>>>(Wc, bc, out, N_NODES);
}

// round 11
// speedup vs baseline: 6.0387x; 1.3710x over previous
#include <cuda_runtime.h>
#include <cuda_fp16.h>
#include <cstdint>

#define N_NODES 100000
#define N_EDGES 1600000
#define HID 128
#define NCLS 47
#define NBLK 391                                  // ceil(N_NODES/256)

// ---------------- scratch (static device globals; no runtime allocation) ----
__device__ __half g_yh[(size_t)N_NODES * HID];   // GEMM output fp16 (gather source)
__device__ __half g_hh[(size_t)N_NODES * HID];   // post-activation hidden fp16
__device__ __half g_wt0[HID * HID];              // W0^T fp16  [n][k]
__device__ __half g_wt1[HID * HID];              // W1^T fp16  [n][k]
__device__ __half g_wtc[64 * HID];               // Wc^T fp16  [n][k], rows 47..63 = 0
__device__ float  g_cs[N_NODES];
__device__ float  g_cd[N_NODES];
__device__ int    g_outdeg[N_NODES];
__device__ int    g_indeg [N_NODES];
__device__ int    g_cursor[N_NODES];
__device__ int    g_rowstart[N_NODES + 1];
__device__ int    g_csrc[N_EDGES];
__device__ int    g_bsum[NBLK];
__device__ int    g_boff[NBLK];

// ---------------- degree / CSR pipeline ------------------------------------
__global__ void zero_counts_kernel() {
    int i = blockIdx.x * blockDim.x + threadIdx.x;
    if (i < N_NODES) { g_outdeg[i] = 0; g_indeg[i] = 0; g_cursor[i] = 0; }
}

__global__ void degree_kernel(const int* __restrict__ edges) {
    int i = blockIdx.x * blockDim.x + threadIdx.x;
    if (i < N_EDGES) {
        atomicAdd(&g_outdeg[edges[i]], 1);
        atomicAdd(&g_indeg [edges[N_EDGES + i]], 1);
    }
}

// ---- W pre-transpose + fp16 convert (W0, W1, Wc) --------------------------
__global__ void prep_w_kernel(const float* __restrict__ W0,
                              const float* __restrict__ W1,
                              const float* __restrict__ Wc) {
    int idx = blockIdx.x * 256 + threadIdx.x;
    if (idx < HID * HID) {
        int n = idx >> 7, k = idx & 127;
        g_wt0[idx] = __float2half_rn(W0[k * 128 + n]);
        g_wt1[idx] = __float2half_rn(W1[k * 128 + n]);
    }
    if (idx < 64 * HID) {
        int n = idx >> 7, k = idx & 127;
        g_wtc[idx] = (n < NCLS) ? __float2half_rn(Wc[k * NCLS + n])
                                : __float2half_rn(0.f);
    }
}

// ---- fused: finish degrees (cs/cd) + per-block indeg sums -----------------
__global__ void __launch_bounds__(256) finish_deg_bsum_kernel() {
    __shared__ int sm[8];
    int i = blockIdx.x * 256 + threadIdx.x;
    int v = 0;
    if (i < N_NODES) {
        int od = g_outdeg[i];
        v = g_indeg[i];
        g_cs[i] = rsqrtf(fmaxf((float)od, 1.f));
        g_cd[i] = rsqrtf(fmaxf((float)v,  1.f));
    }
    int s = v;
#pragma unroll
    for (int off = 16; off > 0; off >>= 1)
        s += __shfl_down_sync(0xffffffffu, s, off);
    if ((threadIdx.x & 31) == 0) sm[threadIdx.x >> 5] = s;
    __syncthreads();
    if (threadIdx.x < 8) {
        int t = sm[threadIdx.x];
#pragma unroll
        for (int off = 4; off > 0; off >>= 1)
            t += __shfl_down_sync(0xffu, t, off);
        if (threadIdx.x == 0) g_bsum[blockIdx.x] = t;
    }
}

// ---- scan phase 2 ----------------------------------------------------------
__global__ void __launch_bounds__(512) scan_bsum_kernel() {
    __shared__ int part[512];
    int t = threadIdx.x;
    part[t] = (t < NBLK) ? g_bsum[t] : 0;
    __syncthreads();
    for (int off = 1; off < 512; off <<= 1) {
        int v = (t >= off) ? part[t - off] : 0;
        __syncthreads();
        part[t] += v;
        __syncthreads();
    }
    if (t < NBLK) g_boff[t] = (t == 0) ? 0 : part[t - 1];
    if (t == 0) g_rowstart[N_NODES] = N_EDGES;
}

// ---- scan phase 3 ----------------------------------------------------------
__global__ void __launch_bounds__(256) rowstart_kernel() {
    __shared__ int part[256];
    int t = threadIdx.x;
    int i = blockIdx.x * 256 + t;
    int v = (i < N_NODES) ? g_indeg[i] : 0;
    part[t] = v;
    __syncthreads();
    for (int off = 1; off < 256; off <<= 1) {
        int u = (t >= off) ? part[t - off] : 0;
        __syncthreads();
        part[t] += u;
        __syncthreads();
    }
    if (i < N_NODES)
        g_rowstart[i] = g_boff[blockIdx.x] + part[t] - v;
}

__global__ void fill_csr_kernel(const int* __restrict__ edges) {
    int i = blockIdx.x * blockDim.x + threadIdx.x;
    if (i < N_EDGES) {
        int s = edges[i];
        int d = edges[N_EDGES + i];
        int pos = g_rowstart[d] + atomicAdd(&g_cursor[d], 1);
        g_csrc[pos] = s;
    }
}

// ---------------- tensor-core GEMM: Yh = fp16((A*c_src) @ W) ---------------
// Block 64x128, two 64-K chunks, software-pipelined (chunk-1 global loads
// issued before chunk-0 MMA). 8 warps (2x4), warp tile 32x32, m16n8k16.
__global__ void __launch_bounds__(256) gemm_mma_kernel(
    const float* __restrict__ X, int layer, int M)
{
    __shared__ __align__(16) __half Ah[64][72];
    __shared__ __align__(16) __half Bt[128][72];

    const __half* Wt = layer ? g_wt1 : g_wt0;

    int tid  = threadIdx.x;
    int lane = tid & 31;
    int warp = tid >> 5;
    int wm   = warp >> 2;
    int wn   = warp & 3;
    int g    = lane >> 2;
    int tq   = lane & 3;
    int row0 = blockIdx.x * 64;

    uint32_t ahBase = (uint32_t)__cvta_generic_to_shared(&Ah[0][0]);
    uint32_t btBase = (uint32_t)__cvta_generic_to_shared(&Bt[0][0]);
    int atrow = lane & 15;
    int athalf = (lane >> 4) * 8;
    uint32_t aAddr[2];
#pragma unroll
    for (int ma = 0; ma < 2; ma++)
        aAddr[ma] = ahBase + ((wm * 32 + ma * 16 + atrow) * 72 + athalf) * 2;
    int btrow = (lane & 7) + ((lane >> 4) << 3);
    int bthalf = ((lane >> 3) & 1) * 8;
    uint32_t bAddr[2];
#pragma unroll
    for (int p = 0; p < 2; p++)
        bAddr[p] = btBase + ((wn * 32 + p * 16 + btrow) * 72 + bthalf) * 2;

    // A-task geometry (2 tasks/thread), B-task geometry (4 tasks/thread)
    int ar[2], akb[2];
#pragma unroll
    for (int t = 0; t < 2; t++) {
        int id = tid + t * 256;
        ar[t]  = id >> 3;
        akb[t] = (id & 7) * 8;
    }
    int bn[4], bkb[4];
#pragma unroll
    for (int t = 0; t < 4; t++) {
        int id = tid + t * 256;
        bn[t]  = id >> 3;
        bkb[t] = (id & 7) * 8;
    }

    float acc[2][4][4];
#pragma unroll
    for (int ma = 0; ma < 2; ma++)
#pragma unroll
        for (int na = 0; na < 4; na++)
#pragma unroll
            for (int q = 0; q < 4; q++) acc[ma][na][q] = 0.f;

    uint4 ast[2], bst[4];

    // ---- load chunk 0 ----
#pragma unroll
    for (int t = 0; t < 2; t++) {
        int grow = row0 + ar[t];
        __half2 h[4];
        if (grow < M) {
            float s = g_cs[grow];
            if (!layer) {
                const float4* p = (const float4*)(X + (size_t)grow * 128 + akb[t]);
                float4 v0 = p[0], v1 = p[1];
                h[0] = __floats2half2_rn(v0.x * s, v0.y * s);
                h[1] = __floats2half2_rn(v0.z * s, v0.w * s);
                h[2] = __floats2half2_rn(v1.x * s, v1.y * s);
                h[3] = __floats2half2_rn(v1.z * s, v1.w * s);
            } else {
                uint4 u = *(const uint4*)(g_hh + (size_t)grow * 128 + akb[t]);
                const __half2* hp = (const __half2*)&u;
#pragma unroll
                for (int q = 0; q < 4; q++) {
                    float2 f = __half22float2(hp[q]);
                    h[q] = __floats2half2_rn(f.x * s, f.y * s);
                }
            }
        } else {
            __half2 z = __floats2half2_rn(0.f, 0.f);
            h[0] = z; h[1] = z; h[2] = z; h[3] = z;
        }
        ast[t].x = *(uint32_t*)&h[0]; ast[t].y = *(uint32_t*)&h[1];
        ast[t].z = *(uint32_t*)&h[2]; ast[t].w = *(uint32_t*)&h[3];
    }
#pragma unroll
    for (int t = 0; t < 4; t++)
        bst[t] = *(const uint4*)(Wt + (size_t)bn[t] * 128 + bkb[t]);

#pragma unroll
    for (int t = 0; t < 2; t++) *(uint4*)&Ah[ar[t]][akb[t]] = ast[t];
#pragma unroll
    for (int t = 0; t < 4; t++) *(uint4*)&Bt[bn[t]][bkb[t]] = bst[t];
    __syncthreads();

    // ---- prefetch chunk 1 into registers ----
#pragma unroll
    for (int t = 0; t < 2; t++) {
        int grow = row0 + ar[t];
        __half2 h[4];
        if (grow < M) {
            float s = g_cs[grow];
            if (!layer) {
                const float4* p = (const float4*)(X + (size_t)grow * 128 + 64 + akb[t]);
                float4 v0 = p[0], v1 = p[1];
                h[0] = __floats2half2_rn(v0.x * s, v0.y * s);
                h[1] = __floats2half2_rn(v0.z * s, v0.w * s);
                h[2] = __floats2half2_rn(v1.x * s, v1.y * s);
                h[3] = __floats2half2_rn(v1.z * s, v1.w * s);
            } else {
                uint4 u = *(const uint4*)(g_hh + (size_t)grow * 128 + 64 + akb[t]);
                const __half2* hp = (const __half2*)&u;
#pragma unroll
                for (int q = 0; q < 4; q++) {
                    float2 f = __half22float2(hp[q]);
                    h[q] = __floats2half2_rn(f.x * s, f.y * s);
                }
            }
        } else {
            __half2 z = __floats2half2_rn(0.f, 0.f);
            h[0] = z; h[1] = z; h[2] = z; h[3] = z;
        }
        ast[t].x = *(uint32_t*)&h[0]; ast[t].y = *(uint32_t*)&h[1];
        ast[t].z = *(uint32_t*)&h[2]; ast[t].w = *(uint32_t*)&h[3];
    }
#pragma unroll
    for (int t = 0; t < 4; t++)
        bst[t] = *(const uint4*)(Wt + (size_t)bn[t] * 128 + 64 + bkb[t]);

    // ---- MMA over chunk 0 / store chunk 1 / MMA over chunk 1 ----
#pragma unroll
    for (int chunk = 0; chunk < 2; chunk++) {
#pragma unroll
        for (int ks = 0; ks < 64; ks += 16) {
            uint32_t a[2][4], b[4][2];
#pragma unroll
            for (int ma = 0; ma < 2; ma++) {
                asm volatile(
                    "ldmatrix.sync.aligned.m8n8.x4.shared.b16 {%0,%1,%2,%3}, [%4];\n"
                    : "=r"(a[ma][0]), "=r"(a[ma][1]), "=r"(a[ma][2]), "=r"(a[ma][3])
                    : "r"(aAddr[ma] + ks * 2));
            }
#pragma unroll
            for (int p = 0; p < 2; p++) {
                uint32_t r0, r1, r2, r3;
                asm volatile(
                    "ldmatrix.sync.aligned.m8n8.x4.shared.b16 {%0,%1,%2,%3}, [%4];\n"
                    : "=r"(r0), "=r"(r1), "=r"(r2), "=r"(r3)
                    : "r"(bAddr[p] + ks * 2));
                b[p * 2 + 0][0] = r0; b[p * 2 + 0][1] = r1;
                b[p * 2 + 1][0] = r2; b[p * 2 + 1][1] = r3;
            }
#pragma unroll
            for (int ma = 0; ma < 2; ma++)
#pragma unroll
                for (int na = 0; na < 4; na++) {
                    asm volatile(
                        "mma.sync.aligned.m16n8k16.row.col.f32.f16.f16.f32 "
                        "{%0,%1,%2,%3}, {%4,%5,%6,%7}, {%8,%9}, {%0,%1,%2,%3};\n"
                        : "+f"(acc[ma][na][0]), "+f"(acc[ma][na][1]),
                          "+f"(acc[ma][na][2]), "+f"(acc[ma][na][3])
                        : "r"(a[ma][0]), "r"(a[ma][1]), "r"(a[ma][2]), "r"(a[ma][3]),
                          "r"(b[na][0]), "r"(b[na][1]));
                }
        }
        if (chunk == 0) {
            __syncthreads();
#pragma unroll
            for (int t = 0; t < 2; t++) *(uint4*)&Ah[ar[t]][akb[t]] = ast[t];
#pragma unroll
            for (int t = 0; t < 4; t++) *(uint4*)&Bt[bn[t]][bkb[t]] = bst[t];
            __syncthreads();
        }
    }

    // ---- epilogue: fp32 acc -> fp16 g_yh ----
#pragma unroll
    for (int ma = 0; ma < 2; ma++) {
        int r0 = row0 + wm * 32 + ma * 16 + g;
        int r1 = r0 + 8;
#pragma unroll
        for (int na = 0; na < 4; na++) {
            int col = wn * 32 + na * 8 + tq * 2;
            if (r0 < M)
                *(__half2*)(g_yh + (size_t)r0 * 128 + col) =
                    __floats2half2_rn(acc[ma][na][0], acc[ma][na][1]);
            if (r1 < M)
                *(__half2*)(g_yh + (size_t)r1 * 128 + col) =
                    __floats2half2_rn(acc[ma][na][2], acc[ma][na][3]);
        }
    }
}

// ---------------- CSR gather (fp16 src) + scale + bias + relu -> fp16 ------
__global__ void __launch_bounds__(256) gather_kernel(const float* __restrict__ b) {
    int w    = blockIdx.x * 8 + (threadIdx.x >> 5);
    int lane = threadIdx.x & 31;
    if (w >= N_NODES) return;

    int beg = __ldg(&g_rowstart[w]);
    int end = __ldg(&g_rowstart[w + 1]);

    float4 acc = make_float4(0.f, 0.f, 0.f, 0.f);

    for (int base = beg; base < end; base += 32) {
        int n   = end - base;
        int m   = n < 32 ? n : 32;
        int idx = (lane < m) ? __ldg(&g_csrc[base + lane]) : 0;

        int j = 0;
        for (; j + 4 <= m; j += 4) {
            int s0 = __shfl_sync(0xffffffffu, idx, j + 0);
            int s1 = __shfl_sync(0xffffffffu, idx, j + 1);
            int s2 = __shfl_sync(0xffffffffu, idx, j + 2);
            int s3 = __shfl_sync(0xffffffffu, idx, j + 3);
            uint2 r0 = *(const uint2*)(g_yh + (size_t)s0 * 128 + lane * 4);
            uint2 r1 = *(const uint2*)(g_yh + (size_t)s1 * 128 + lane * 4);
            uint2 r2 = *(const uint2*)(g_yh + (size_t)s2 * 128 + lane * 4);
            uint2 r3 = *(const uint2*)(g_yh + (size_t)s3 * 128 + lane * 4);
            float2 a0 = __half22float2(*(const __half2*)&r0.x);
            float2 b0_ = __half22float2(*(const __half2*)&r0.y);
            float2 a1 = __half22float2(*(const __half2*)&r1.x);
            float2 b1_ = __half22float2(*(const __half2*)&r1.y);
            float2 a2 = __half22float2(*(const __half2*)&r2.x);
            float2 b2_ = __half22float2(*(const __half2*)&r2.y);
            float2 a3 = __half22float2(*(const __half2*)&r3.x);
            float2 b3_ = __half22float2(*(const __half2*)&r3.y);
            acc.x += (a0.x + a1.x) + (a2.x + a3.x);
            acc.y += (a0.y + a1.y) + (a2.y + a3.y);
            acc.z += (b0_.x + b1_.x) + (b2_.x + b3_.x);
            acc.w += (b0_.y + b1_.y) + (b2_.y + b3_.y);
        }
        for (; j < m; j++) {
            int s = __shfl_sync(0xffffffffu, idx, j);
            uint2 r = *(const uint2*)(g_yh + (size_t)s * 128 + lane * 4);
            float2 a = __half22float2(*(const __half2*)&r.x);
            float2 c = __half22float2(*(const __half2*)&r.y);
            acc.x += a.x; acc.y += a.y; acc.z += c.x; acc.w += c.y;
        }
    }

    float c = g_cd[w];
    float4 bb = *(const float4*)(b + lane * 4);
    __half2 o0 = __floats2half2_rn(fmaxf(fmaf(acc.x, c, bb.x), 0.f),
                                   fmaxf(fmaf(acc.y, c, bb.y), 0.f));
    __half2 o1 = __floats2half2_rn(fmaxf(fmaf(acc.z, c, bb.z), 0.f),
                                   fmaxf(fmaf(acc.w, c, bb.w), 0.f));
    uint2 pack;
    pack.x = *(uint32_t*)&o0;
    pack.y = *(uint32_t*)&o1;
    *(uint2*)(g_hh + (size_t)w * 128 + lane * 4) = pack;
}

// ---------------- classifier (tensor core): out = g_hh @ Wc + bc -----------
// Block 64 rows x 64 cols (47 real). K=128 staged whole. 8 warps (2x4),
// warp tile 32x16. Row stride 136 halves -> conflict-free ldmatrix.
__global__ void __launch_bounds__(256) cls_mma_kernel(
    const float* __restrict__ bc, float* __restrict__ out, int M)
{
    __shared__ __align__(16) __half Ah[64][136];
    __shared__ __align__(16) __half Bt[64][136];

    int tid  = threadIdx.x;
    int lane = tid & 31;
    int warp = tid >> 5;
    int wm   = warp >> 2;     // 0..1
    int wn   = warp & 3;      // 0..3
    int g    = lane >> 2;
    int tq   = lane & 3;
    int row0 = blockIdx.x * 64;

    // stage A: 64 rows x 128 halves (16 uint4 per row) = 1024 tasks, 4/thread
#pragma unroll
    for (int t = 0; t < 4; t++) {
        int id = tid + t * 256;
        int r  = id >> 4;               // 0..63
        int kb = (id & 15) * 8;         // 0..120
        int grow = row0 + r;
        uint4 v = make_uint4(0u, 0u, 0u, 0u);
        if (grow < M) v = *(const uint4*)(g_hh + (size_t)grow * 128 + kb);
        *(uint4*)&Ah[r][kb] = v;
    }
    // stage Bt: 64 n x 128 k = 1024 uint4 tasks, 4/thread  (BUGFIX: was 2)
#pragma unroll
    for (int t = 0; t < 4; t++) {
        int id = tid + t * 256;
        int n  = id >> 4;               // 0..63
        int kb = (id & 15) * 8;         // 0..120
        *(uint4*)&Bt[n][kb] = *(const uint4*)(g_wtc + (size_t)n * 128 + kb);
    }
    __syncthreads();

    uint32_t ahBase = (uint32_t)__cvta_generic_to_shared(&Ah[0][0]);
    uint32_t btBase = (uint32_t)__cvta_generic_to_shared(&Bt[0][0]);
    int atrow = lane & 15;
    int athalf = (lane >> 4) * 8;
    uint32_t aAddr[2];
#pragma unroll
    for (int ma = 0; ma < 2; ma++)
        aAddr[ma] = ahBase + ((wm * 32 + ma * 16 + atrow) * 136 + athalf) * 2;
    int btrow = (lane & 7) + ((lane >> 4) << 3);
    int bthalf = ((lane >> 3) & 1) * 8;
    uint32_t bAddr = btBase + ((wn * 16 + btrow) * 136 + bthalf) * 2;

    float acc[2][2][4];
#pragma unroll
    for (int ma = 0; ma < 2; ma++)
#pragma unroll
        for (int na = 0; na < 2; na++)
#pragma unroll
            for (int q = 0; q < 4; q++) acc[ma][na][q] = 0.f;

#pragma unroll
    for (int ks = 0; ks < 128; ks += 16) {
        uint32_t a[2][4], b[2][2];
#pragma unroll
        for (int ma = 0; ma < 2; ma++) {
            asm volatile(
                "ldmatrix.sync.aligned.m8n8.x4.shared.b16 {%0,%1,%2,%3}, [%4];\n"
                : "=r"(a[ma][0]), "=r"(a[ma][1]), "=r"(a[ma][2]), "=r"(a[ma][3])
                : "r"(aAddr[ma] + ks * 2));
        }
        {
            uint32_t r0, r1, r2, r3;
            asm volatile(
                "ldmatrix.sync.aligned.m8n8.x4.shared.b16 {%0,%1,%2,%3}, [%4];\n"
                : "=r"(r0), "=r"(r1), "=r"(r2), "=r"(r3)
                : "r"(bAddr + ks * 2));
            b[0][0] = r0; b[0][1] = r1;
            b[1][0] = r2; b[1][1] = r3;
        }
#pragma unroll
        for (int ma = 0; ma < 2; ma++)
#pragma unroll
            for (int na = 0; na < 2; na++) {
                asm volatile(
                    "mma.sync.aligned.m16n8k16.row.col.f32.f16.f16.f32 "
                    "{%0,%1,%2,%3}, {%4,%5,%6,%7}, {%8,%9}, {%0,%1,%2,%3};\n"
                    : "+f"(acc[ma][na][0]), "+f"(acc[ma][na][1]),
                      "+f"(acc[ma][na][2]), "+f"(acc[ma][na][3])
                    : "r"(a[ma][0]), "r"(a[ma][1]), "r"(a[ma][2]), "r"(a[ma][3]),
                      "r"(b[na][0]), "r"(b[na][1]));
            }
    }

    // epilogue: add bias, write fp32 with col<47 guard
#pragma unroll
    for (int ma = 0; ma < 2; ma++) {
        int r0 = row0 + wm * 32 + ma * 16 + g;
        int r1 = r0 + 8;
#pragma unroll
        for (int na = 0; na < 2; na++) {
            int col = wn * 16 + na * 8 + tq * 2;
            float bb0 = (col < NCLS)     ? bc[col]     : 0.f;
            float bb1 = (col + 1 < NCLS) ? bc[col + 1] : 0.f;
            if (r0 < M) {
                if (col < NCLS)     out[(size_t)r0 * NCLS + col]     = acc[ma][na][0] + bb0;
                if (col + 1 < NCLS) out[(size_t)r0 * NCLS + col + 1] = acc[ma][na][1] + bb1;
            }
            if (r1 < M) {
                if (col < NCLS)     out[(size_t)r1 * NCLS + col]     = acc[ma][na][2] + bb0;
                if (col + 1 < NCLS) out[(size_t)r1 * NCLS + col + 1] = acc[ma][na][3] + bb1;
            }
        }
    }
}

// ---------------- launch ----------------------------------------------------
extern "C" void kernel_launch(void* const* d_in, const int* in_sizes, int n_in,
                              void* d_out, int out_size)
{
    const float* x     = (const float*)d_in[0];
    const int*   edges = (const int*)  d_in[1];
    const float* W0    = (const float*)d_in[2];
    const float* b0    = (const float*)d_in[3];
    const float* W1    = (const float*)d_in[4];
    const float* b1    = (const float*)d_in[5];
    const float* Wc    = (const float*)d_in[6];
    const float* bc    = (const float*)d_in[7];
    float* out = (float*)d_out;

    const int nodeBlocks   = (N_NODES + 255) / 256;      // 391
    const int edgeBlocks   = (N_EDGES + 255) / 256;      // 6250
    const int gemmBlocks   = (N_NODES + 63) / 64;        // 1563
    const int gatherBlocks = (N_NODES + 7) / 8;          // 12500

    // normalization coefficients + CSR build + weight prep
    zero_counts_kernel<<<nodeBlocks, 256>>>();
    degree_kernel<<<edgeBlocks, 256>>>(edges);
    prep_w_kernel<<<64, 256>>>(W0, W1, Wc);
    finish_deg_bsum_kernel<<<NBLK, 256>>>();
    scan_bsum_kernel<<<1, 512>>>();
    rowstart_kernel<<<NBLK, 256>>>();
    fill_csr_kernel<<<edgeBlocks, 256>>>(edges);

    // layer 0
    gemm_mma_kernel<<<gemmBlocks, 256>>>(x, 0, N_NODES);
    gather_kernel<<<gatherBlocks, 256>>>(b0);

    // layer 1
    gemm_mma_kernel<<<gemmBlocks, 256>>>(nullptr, 1, N_NODES);
    gather_kernel<<<gatherBlocks, 256>>>(b1);

    // classifier (tensor core)
    cls_mma_kernel<<<gemmBlocks, 256>>>(bc, out, N_NODES);
}